// round 1
// baseline (speedup 1.0000x reference)
#include <cuda_runtime.h>
#include <math.h>

// ---------------- problem constants ----------------
constexpr int CB  = 4;      // batch
constexpr int CC  = 512;    // channels
constexpr int CHH = 32;     // H
constexpr int CWW = 32;     // W
constexpr int CHW = 1024;   // H*W
constexpr int CNH = 8;      // heads
constexpr int CHD = 64;     // head dim
constexpr int NPR = 8;      // prompt tokens
constexpr int CN  = 1032;   // total tokens
constexpr int HID = 1024;   // mlp hidden
constexpr float EPS = 1e-5f;

// ---------------- scratch (static device memory; no allocations) ----------------
__device__ float g_dw1 [CB*CC*CHW];
__device__ float g_dsf [CB*CC*CHW];
__device__ float g_pp1t[CB*CHW*CC];
__device__ float g_pp2t[CB*CHW*CC];
__device__ float g_ds  [CB*CHW];
__device__ float g_prompt[CB*NPR*CC];
__device__ float g_jd  [CB*CN];
__device__ float g_jt  [CB*CN*CC];
__device__ float g_x   [CB*CN*CC];
__device__ float g_q   [CB*CN*CC];
__device__ float g_k   [CB*CN*CC];
__device__ float g_v   [CB*CN*CC];
__device__ float g_ao  [CB*CN*CC];
__device__ float g_h   [CB*CN*HID];
__device__ float g_enh [CB*CC*CHW];
__device__ float g_o1c [CB*CC*CHW];
__device__ float g_o1t [CB*CHW*CC];
__device__ float g_o2t [CB*CHW*CC];

__device__ __forceinline__ float gelu_f(float x){
    return 0.5f * x * (1.0f + erff(x * 0.70710678118654752f));
}

// ---------------- depthwise 3x3 conv + BN + GELU (optionally two branches) ----------------
__global__ void k_dwconv_dual(const float* __restrict__ in,
                              const float* __restrict__ w1, const float* __restrict__ bn1,
                              float* __restrict__ out1,
                              const float* __restrict__ w2, const float* __restrict__ bn2,
                              float* __restrict__ out2)
{
    int idx = blockIdx.x * 256 + threadIdx.x;
    if (idx >= CB*CC*CHW) return;
    int p = idx & (CHW-1);
    int c = (idx >> 10) & (CC-1);
    int y = p >> 5, x = p & 31;
    const float* base = in + (size_t)(idx - p);
    float v[9];
#pragma unroll
    for (int ky = 0; ky < 3; ky++)
#pragma unroll
        for (int kx = 0; kx < 3; kx++){
            int yy = y + ky - 1, xx = x + kx - 1;
            v[ky*3+kx] = (yy >= 0 && yy < CHH && xx >= 0 && xx < CWW) ? base[yy*CWW + xx] : 0.f;
        }
    {
        float a = 0.f;
#pragma unroll
        for (int k = 0; k < 9; k++) a += w1[c*9+k] * v[k];
        float s = bn1[c] * rsqrtf(bn1[3*CC+c] + EPS);
        a = a * s + bn1[CC+c] - bn1[2*CC+c] * s;
        out1[idx] = gelu_f(a);
    }
    if (out2){
        float a = 0.f;
#pragma unroll
        for (int k = 0; k < 9; k++) a += w2[c*9+k] * v[k];
        float s = bn2[c] * rsqrtf(bn2[3*CC+c] + EPS);
        a = a * s + bn2[CC+c] - bn2[2*CC+c] * s;
        out2[idx] = gelu_f(a);
    }
}

// ---------------- transposes ----------------
// in: [B][C][HW]  -> out tokens: [B][tokTotal][C] at token = tokOff + p
__global__ void k_cp_to_tok(const float* __restrict__ in, float* __restrict__ out,
                            int tokTotal, int tokOff)
{
    __shared__ float tile[32][33];
    int b = blockIdx.z;
    int p0 = blockIdx.x * 32, c0 = blockIdx.y * 32;
    int tx = threadIdx.x, ty = threadIdx.y;
#pragma unroll
    for (int i = 0; i < 4; i++){
        int c = c0 + ty + i*8;
        tile[ty + i*8][tx] = in[((size_t)b*CC + c)*CHW + p0 + tx];
    }
    __syncthreads();
#pragma unroll
    for (int i = 0; i < 4; i++){
        int p = p0 + ty + i*8;
        out[((size_t)b*tokTotal + tokOff + p)*CC + c0 + tx] = tile[tx][ty + i*8];
    }
}

// in tokens: [B][tokTotal][C] (token = tokOff + p) -> out [B][C][HW]
__global__ void k_tok_to_cp(const float* __restrict__ in, float* __restrict__ out,
                            int tokTotal, int tokOff)
{
    __shared__ float tile[32][33];
    int b = blockIdx.z;
    int p0 = blockIdx.x * 32, c0 = blockIdx.y * 32;
    int tx = threadIdx.x, ty = threadIdx.y;
#pragma unroll
    for (int i = 0; i < 4; i++){
        int p = p0 + ty + i*8;
        tile[ty + i*8][tx] = in[((size_t)b*tokTotal + tokOff + p)*CC + c0 + tx];
    }
    __syncthreads();
#pragma unroll
    for (int i = 0; i < 4; i++){
        int c = c0 + ty + i*8;
        out[((size_t)b*CC + c)*CHW + p0 + tx] = tile[tx][ty + i*8];
    }
}

// ---------------- NT GEMM:  C[m,n] = sum_k A[m,k] * B[n,k]  (both row-major) ----------------
// EPI: 0 plain, 1 bn+gelu, 2 bias+gelu, 3 bias+residual, 4 residual
template<int EPI>
__global__ void __launch_bounds__(256) k_gemm_nt(const float* __restrict__ A,
                                                 const float* __restrict__ Bw,
                                                 float* Cmat, int M, int N, int K,
                                                 const float* __restrict__ ep,
                                                 const float* res)
{
    __shared__ float As[8][128];
    __shared__ float Bs[8][128];
    int tid = threadIdx.x;
    int m0 = blockIdx.y * 128, n0 = blockIdx.x * 128;
    int tx = tid & 15, ty = tid >> 4;
    int lr = tid >> 1;
    int lc = (tid & 1) * 4;
    bool aval = (m0 + lr) < M;
    const float* Aload = A  + (size_t)(m0 + lr) * K + lc;
    const float* Bload = Bw + (size_t)(n0 + lr) * K + lc;

    float acc[8][8];
#pragma unroll
    for (int i = 0; i < 8; i++)
#pragma unroll
        for (int j = 0; j < 8; j++) acc[i][j] = 0.f;

    for (int k0 = 0; k0 < K; k0 += 8){
        float4 av = aval ? *(const float4*)(Aload + k0) : make_float4(0.f,0.f,0.f,0.f);
        float4 bv = *(const float4*)(Bload + k0);
        As[lc+0][lr] = av.x; As[lc+1][lr] = av.y; As[lc+2][lr] = av.z; As[lc+3][lr] = av.w;
        Bs[lc+0][lr] = bv.x; Bs[lc+1][lr] = bv.y; Bs[lc+2][lr] = bv.z; Bs[lc+3][lr] = bv.w;
        __syncthreads();
#pragma unroll
        for (int kk = 0; kk < 8; kk++){
            float a[8], b[8];
#pragma unroll
            for (int i = 0; i < 8; i++) a[i] = As[kk][ty*8 + i];
#pragma unroll
            for (int j = 0; j < 8; j++) b[j] = Bs[kk][tx*8 + j];
#pragma unroll
            for (int i = 0; i < 8; i++)
#pragma unroll
                for (int j = 0; j < 8; j++) acc[i][j] += a[i] * b[j];
        }
        __syncthreads();
    }

#pragma unroll
    for (int i = 0; i < 8; i++){
        int row = m0 + ty*8 + i;
        if (row >= M) continue;
        size_t base = (size_t)row * N;
#pragma unroll
        for (int j = 0; j < 8; j++){
            int col = n0 + tx*8 + j;
            float vv = acc[i][j];
            if (EPI == 1){
                float s = ep[col] * rsqrtf(ep[3*N+col] + EPS);
                vv = vv * s + ep[N+col] - ep[2*N+col] * s;
                vv = gelu_f(vv);
            } else if (EPI == 2){
                vv = gelu_f(vv + ep[col]);
            } else if (EPI == 3){
                vv = res[base + col] + vv + ep[col];
            } else if (EPI == 4){
                vv = res[base + col] + vv;
            }
            Cmat[base + col] = vv;
        }
    }
}

// ---------------- geometry prior: 512->1 projection ----------------
__global__ void k_gp_pw(const float* __restrict__ dsf, const float* __restrict__ w,
                        const float* __restrict__ bias, float* __restrict__ ds)
{
    int t = blockIdx.x * 256 + threadIdx.x;
    if (t >= CB*CHW) return;
    int b = t >> 10, p = t & (CHW-1);
    float acc = 0.f;
    for (int c = 0; c < CC; c++)
        acc += w[c] * dsf[((size_t)b*CC + c)*CHW + p];
    ds[t] = acc + bias[0];
}

// ---------------- prompt: pool + embed + LN ----------------
__global__ void k_prompt(const float* __restrict__ pp2t, const float* __restrict__ pe,
                         const float* __restrict__ lnp, float* __restrict__ out)
{
    int b = blockIdx.x >> 3, pr = blockIdx.x & 7;
    int iy = pr >> 2, ix = pr & 3;
    int t = threadIdx.x;
    float a0 = 0.f, a1 = 0.f;
    for (int py = 0; py < 16; py++)
        for (int px = 0; px < 8; px++){
            int p = (iy*16 + py)*CWW + ix*8 + px;
            const float* base = pp2t + ((size_t)b*CHW + p)*CC;
            a0 += base[t];
            a1 += base[t + 256];
        }
    a0 = a0 * (1.f/128.f) + pe[pr*CC + t];
    a1 = a1 * (1.f/128.f) + pe[pr*CC + t + 256];
    __shared__ float rs[256], rq[256];
    rs[t] = a0 + a1; rq[t] = a0*a0 + a1*a1;
    __syncthreads();
    for (int s = 128; s > 0; s >>= 1){
        if (t < s){ rs[t] += rs[t+s]; rq[t] += rq[t+s]; }
        __syncthreads();
    }
    float mean = rs[0] * (1.f/512.f);
    float var  = rq[0] * (1.f/512.f) - mean*mean;
    float inv  = rsqrtf(var + EPS);
    size_t o = ((size_t)b*NPR + pr) * CC;
    out[o + t]       = (a0 - mean) * inv * lnp[t]       + lnp[CC + t];
    out[o + t + 256] = (a1 - mean) * inv * lnp[t + 256] + lnp[CC + t + 256];
}

// ---------------- joint depth scalar per token ----------------
__global__ void k_jd(const float* __restrict__ ds, float* __restrict__ jd)
{
    int t = blockIdx.x * 256 + threadIdx.x;
    if (t >= CB*CN) return;
    int b = t / CN, n = t % CN;
    if (n >= NPR){
        jd[t] = ds[b*CHW + (n - NPR)];
    } else {
        int iy = n >> 2, ix = n & 3;
        float acc = 0.f;
        for (int py = 0; py < 16; py++)
            for (int px = 0; px < 8; px++)
                acc += ds[b*CHW + (iy*16 + py)*CWW + ix*8 + px];
        jd[t] = acc * (1.f/128.f);
    }
}

// ---------------- copy prompt tokens into jt ----------------
__global__ void k_copy_prompt(const float* __restrict__ pr, float* __restrict__ jt)
{
    int idx = blockIdx.x * 256 + threadIdx.x;
    if (idx >= CB*NPR*CC) return;
    int b = idx / (NPR*CC), r = idx % (NPR*CC);
    jt[(size_t)b*CN*CC + r] = pr[(size_t)b*NPR*CC + r];
}

// ---------------- layernorm over C per token ----------------
__global__ void k_ln(const float* __restrict__ in, const float* __restrict__ p,
                     float* __restrict__ out)
{
    int tok = blockIdx.x;
    const float* row = in + (size_t)tok * CC;
    int t = threadIdx.x;
    float v0 = row[t], v1 = row[t + 256];
    __shared__ float rs[256], rq[256];
    rs[t] = v0 + v1; rq[t] = v0*v0 + v1*v1;
    __syncthreads();
    for (int s = 128; s > 0; s >>= 1){
        if (t < s){ rs[t] += rs[t+s]; rq[t] += rq[t+s]; }
        __syncthreads();
    }
    float mean = rs[0] * (1.f/512.f);
    float var  = rq[0] * (1.f/512.f) - mean*mean;
    float inv  = rsqrtf(var + EPS);
    size_t o = (size_t)tok * CC;
    out[o + t]       = (v0 - mean) * inv * p[t]       + p[CC + t];
    out[o + t + 256] = (v1 - mean) * inv * p[t + 256] + p[CC + t + 256];
}

// ---------------- attention (streaming softmax, analytic bias) ----------------
__device__ __forceinline__ void tok_coord(int n, float& cy, float& cx){
    if (n < NPR){ cy = (float)(n >> 2); cx = (float)(n & 3) * (1.f/3.f); }
    else { int m = n - NPR; cy = (float)(m >> 5) * (1.f/31.f); cx = (float)(m & 31) * (1.f/31.f); }
}

constexpr int ATTN_SMEM = (64*68 + 64*65 + 64*64) * 4;  // Qs + KT/P + Vs = 50432 B

__global__ void __launch_bounds__(256) k_attn(const float* __restrict__ qg,
                                              const float* __restrict__ kg,
                                              const float* __restrict__ vg,
                                              const float* __restrict__ jd,
                                              const float* __restrict__ gw,
                                              float* __restrict__ ao)
{
    extern __shared__ float sm[];
    float* Qs = sm;                 // [64][68]
    float* KP = sm + 64*68;         // K^T [64 kk][65]  /  P [64 rows][65]
    float* Vs = KP + 64*65;         // [64][64]
    int b = blockIdx.z, h = blockIdx.y, q0 = blockIdx.x * 64;
    int tid = threadIdx.x, tx = tid & 15, ty = tid >> 4;

    const float decay = logf(1.f - exp2f(-1.f - 0.5f * (float)h));
    const float w0 = gw[0] * decay, w1 = gw[1] * decay;

    for (int e = tid; e < 64*64; e += 256){
        int i = e >> 6, d = e & 63;
        int n = q0 + i;
        Qs[i*68 + d] = (n < CN) ? qg[((size_t)b*CN + n)*CC + h*CHD + d] : 0.f;
    }
    float qy[4], qx[4], qd[4];
#pragma unroll
    for (int r = 0; r < 4; r++){
        int n = q0 + ty*4 + r;
        if (n < CN){ tok_coord(n, qy[r], qx[r]); qd[r] = jd[b*CN + n]; }
        else { qy[r] = qx[r] = qd[r] = 0.f; }
    }
    float mi[4], li[4], O[4][4];
#pragma unroll
    for (int r = 0; r < 4; r++){
        mi[r] = -1e30f; li[r] = 0.f;
#pragma unroll
        for (int s = 0; s < 4; s++) O[r][s] = 0.f;
    }

    for (int kt = 0; kt < 17; kt++){
        int k0 = kt * 64;
        for (int e = tid; e < 64*64; e += 256){
            int j = e >> 6, d = e & 63;
            int n = k0 + j;
            float kv = (n < CN) ? kg[((size_t)b*CN + n)*CC + h*CHD + d] : 0.f;
            KP[d*65 + j] = kv;
            Vs[j*64 + d] = (n < CN) ? vg[((size_t)b*CN + n)*CC + h*CHD + d] : 0.f;
        }
        __syncthreads();

        float ky_[4], kx_[4], kd_[4]; bool kval[4];
#pragma unroll
        for (int s = 0; s < 4; s++){
            int n = k0 + tx*4 + s;
            kval[s] = (n < CN);
            if (kval[s]){ tok_coord(n, ky_[s], kx_[s]); kd_[s] = jd[b*CN + n]; }
            else { ky_[s] = kx_[s] = kd_[s] = 0.f; }
        }

        float S[4][4];
#pragma unroll
        for (int r = 0; r < 4; r++)
#pragma unroll
            for (int s = 0; s < 4; s++) S[r][s] = 0.f;

#pragma unroll 8
        for (int kk = 0; kk < 64; kk++){
            float a[4], bb[4];
#pragma unroll
            for (int r = 0; r < 4; r++) a[r]  = Qs[(ty*4 + r)*68 + kk];
#pragma unroll
            for (int s = 0; s < 4; s++) bb[s] = KP[kk*65 + tx*4 + s];
#pragma unroll
            for (int r = 0; r < 4; r++)
#pragma unroll
                for (int s = 0; s < 4; s++) S[r][s] += a[r] * bb[s];
        }
#pragma unroll
        for (int r = 0; r < 4; r++)
#pragma unroll
            for (int s = 0; s < 4; s++){
                if (kval[s]){
                    float pos = fabsf(qy[r]-ky_[s]) + fabsf(qx[r]-kx_[s]);
                    S[r][s] = S[r][s]*0.125f + w0*pos + w1*fabsf(qd[r]-kd_[s]);
                } else S[r][s] = -1e30f;
            }

        float alpha[4];
#pragma unroll
        for (int r = 0; r < 4; r++){
            float tm = fmaxf(fmaxf(S[r][0], S[r][1]), fmaxf(S[r][2], S[r][3]));
#pragma unroll
            for (int off = 8; off > 0; off >>= 1)
                tm = fmaxf(tm, __shfl_xor_sync(0xffffffffu, tm, off));
            float mn = fmaxf(mi[r], tm);
            alpha[r] = __expf(mi[r] - mn);
            float ssum = 0.f;
#pragma unroll
            for (int s = 0; s < 4; s++){
                S[r][s] = __expf(S[r][s] - mn);
                ssum += S[r][s];
            }
#pragma unroll
            for (int off = 8; off > 0; off >>= 1)
                ssum += __shfl_xor_sync(0xffffffffu, ssum, off);
            li[r] = li[r]*alpha[r] + ssum;
            mi[r] = mn;
#pragma unroll
            for (int s = 0; s < 4; s++) O[r][s] *= alpha[r];
        }
        __syncthreads();   // everyone finished reading KP (K^T)
#pragma unroll
        for (int r = 0; r < 4; r++)
#pragma unroll
            for (int s = 0; s < 4; s++)
                KP[(ty*4 + r)*65 + tx*4 + s] = S[r][s];
        __syncthreads();
#pragma unroll 4
        for (int j = 0; j < 64; j++){
            float pr_[4], vv[4];
#pragma unroll
            for (int r = 0; r < 4; r++) pr_[r] = KP[(ty*4 + r)*65 + j];
#pragma unroll
            for (int s = 0; s < 4; s++) vv[s]  = Vs[j*64 + tx*4 + s];
#pragma unroll
            for (int r = 0; r < 4; r++)
#pragma unroll
                for (int s = 0; s < 4; s++) O[r][s] += pr_[r] * vv[s];
        }
        __syncthreads();
    }

#pragma unroll
    for (int r = 0; r < 4; r++){
        int n = q0 + ty*4 + r;
        if (n < CN){
            float invl = 1.f / li[r];
#pragma unroll
            for (int s = 0; s < 4; s++)
                ao[((size_t)b*CN + n)*CC + h*CHD + tx*4 + s] = O[r][s] * invl;
        }
    }
}

// ---------------- final: out = fused + BN(op_pw output), with transpose ----------------
__global__ void k_final(const float* __restrict__ fused, const float* __restrict__ o2t,
                        const float* __restrict__ bn, float* __restrict__ out)
{
    __shared__ float tile[32][33];
    int b = blockIdx.z;
    int p0 = blockIdx.x * 32, c0 = blockIdx.y * 32;
    int tx = threadIdx.x, ty = threadIdx.y;
#pragma unroll
    for (int i = 0; i < 4; i++){
        int p = p0 + ty + i*8;
        tile[ty + i*8][tx] = o2t[((size_t)b*CHW + p)*CC + c0 + tx];
    }
    __syncthreads();
#pragma unroll
    for (int i = 0; i < 4; i++){
        int c = c0 + ty + i*8;
        float s = bn[c] * rsqrtf(bn[3*CC+c] + EPS);
        float t = bn[CC+c] - bn[2*CC+c] * s;
        size_t idx = ((size_t)b*CC + c)*CHW + p0 + tx;
        out[idx] = fused[idx] + tile[tx][ty + i*8] * s + t;
    }
}

// ---------------- host ----------------
static void launch_gemm(int epi, const float* A, const float* Bw, float* Cm,
                        int M, int N, int K, const float* ep, const float* res)
{
    dim3 g(N/128, (M + 127)/128);
    switch (epi){
        case 0: k_gemm_nt<0><<<g,256>>>(A,Bw,Cm,M,N,K,ep,res); break;
        case 1: k_gemm_nt<1><<<g,256>>>(A,Bw,Cm,M,N,K,ep,res); break;
        case 2: k_gemm_nt<2><<<g,256>>>(A,Bw,Cm,M,N,K,ep,res); break;
        case 3: k_gemm_nt<3><<<g,256>>>(A,Bw,Cm,M,N,K,ep,res); break;
        case 4: k_gemm_nt<4><<<g,256>>>(A,Bw,Cm,M,N,K,ep,res); break;
    }
}

extern "C" void kernel_launch(void* const* d_in, const int* in_sizes, int n_in,
                              void* d_out, int out_size)
{
    const float* fused        = (const float*)d_in[0];
    const float* depth        = (const float*)d_in[1];
    const float* pg_dw_w      = (const float*)d_in[2];
    const float* pg_bn1       = (const float*)d_in[3];
    const float* pg_pw_w      = (const float*)d_in[4];
    const float* pg_bn2       = (const float*)d_in[5];
    const float* prompt_embed = (const float*)d_in[6];
    const float* pg_ln        = (const float*)d_in[7];
    const float* gp_dw_w      = (const float*)d_in[8];
    const float* gp_bn        = (const float*)d_in[9];
    const float* gp_pw_w      = (const float*)d_in[10];
    const float* gp_pw_b      = (const float*)d_in[11];
    const float* gp_weight    = (const float*)d_in[12];
    const float* ln1          = (const float*)d_in[13];
    const float* wq           = (const float*)d_in[14];
    const float* wk           = (const float*)d_in[15];
    const float* wv           = (const float*)d_in[16];
    const float* wo           = (const float*)d_in[17];
    const float* ln2          = (const float*)d_in[18];
    const float* mlp_w1       = (const float*)d_in[19];
    const float* mlp_b1       = (const float*)d_in[20];
    const float* mlp_w2       = (const float*)d_in[21];
    const float* mlp_b2       = (const float*)d_in[22];
    const float* op_dw_w      = (const float*)d_in[23];
    const float* op_bn1       = (const float*)d_in[24];
    const float* op_pw_w      = (const float*)d_in[25];
    const float* op_bn2       = (const float*)d_in[26];

    float *dw1,*dsf,*pp1t,*pp2t,*ds,*prm,*jdb,*jt,*xb,*qb,*kb,*vb,*aob,*hb,*enh,*o1c,*o1t,*o2t;
    cudaGetSymbolAddress((void**)&dw1,  g_dw1);
    cudaGetSymbolAddress((void**)&dsf,  g_dsf);
    cudaGetSymbolAddress((void**)&pp1t, g_pp1t);
    cudaGetSymbolAddress((void**)&pp2t, g_pp2t);
    cudaGetSymbolAddress((void**)&ds,   g_ds);
    cudaGetSymbolAddress((void**)&prm,  g_prompt);
    cudaGetSymbolAddress((void**)&jdb,  g_jd);
    cudaGetSymbolAddress((void**)&jt,   g_jt);
    cudaGetSymbolAddress((void**)&xb,   g_x);
    cudaGetSymbolAddress((void**)&qb,   g_q);
    cudaGetSymbolAddress((void**)&kb,   g_k);
    cudaGetSymbolAddress((void**)&vb,   g_v);
    cudaGetSymbolAddress((void**)&aob,  g_ao);
    cudaGetSymbolAddress((void**)&hb,   g_h);
    cudaGetSymbolAddress((void**)&enh,  g_enh);
    cudaGetSymbolAddress((void**)&o1c,  g_o1c);
    cudaGetSymbolAddress((void**)&o1t,  g_o1t);
    cudaGetSymbolAddress((void**)&o2t,  g_o2t);

    cudaFuncSetAttribute(k_attn, cudaFuncAttributeMaxDynamicSharedMemorySize, ATTN_SMEM);

    dim3 tgrid(CHW/32, CC/32, CB), tblk(32, 8);

    // --- DepthPromptGenerator + GeometryPriorGenerator shared dwconv ---
    k_dwconv_dual<<<(CB*CC*CHW)/256, 256>>>(depth, pg_dw_w, pg_bn1, dw1, gp_dw_w, gp_bn, dsf);
    k_cp_to_tok<<<tgrid, tblk>>>(dw1, pp1t, CHW, 0);
    launch_gemm(1, pp1t, pg_pw_w, pp2t, CB*CHW, CC, CC, pg_bn2, nullptr);   // bn2 + gelu
    k_gp_pw<<<(CB*CHW)/256, 256>>>(dsf, gp_pw_w, gp_pw_b, ds);
    k_prompt<<<CB*NPR, 256>>>(pp2t, prompt_embed, pg_ln, prm);
    k_jd<<<(CB*CN + 255)/256, 256>>>(ds, jdb);

    // --- assemble joint tokens ---
    k_copy_prompt<<<(CB*NPR*CC)/256, 256>>>(prm, jt);
    k_cp_to_tok<<<tgrid, tblk>>>(fused, jt, CN, NPR);

    // --- attention block ---
    k_ln<<<CB*CN, 256>>>(jt, ln1, xb);
    launch_gemm(0, xb, wq, qb, CB*CN, CC, CC, nullptr, nullptr);
    launch_gemm(0, xb, wk, kb, CB*CN, CC, CC, nullptr, nullptr);
    launch_gemm(0, xb, wv, vb, CB*CN, CC, CC, nullptr, nullptr);
    k_attn<<<dim3(17, CNH, CB), 256, ATTN_SMEM>>>(qb, kb, vb, jdb, gp_weight, aob);
    launch_gemm(4, aob, wo, jt, CB*CN, CC, CC, nullptr, jt);                // jt += ao@wo^T

    // --- MLP ---
    k_ln<<<CB*CN, 256>>>(jt, ln2, xb);
    launch_gemm(2, xb, mlp_w1, hb, CB*CN, HID, CC, mlp_b1, nullptr);        // bias + gelu
    launch_gemm(3, hb, mlp_w2, jt, CB*CN, CC, HID, mlp_b2, jt);             // bias + residual

    // --- out_proj ---
    k_tok_to_cp<<<tgrid, tblk>>>(jt, enh, CN, NPR);
    k_dwconv_dual<<<(CB*CC*CHW)/256, 256>>>(enh, op_dw_w, op_bn1, o1c, nullptr, nullptr, nullptr);
    k_cp_to_tok<<<tgrid, tblk>>>(o1c, o1t, CHW, 0);
    launch_gemm(0, o1t, op_pw_w, o2t, CB*CHW, CC, CC, nullptr, nullptr);
    k_final<<<tgrid, tblk>>>(fused, o2t, op_bn2, (float*)d_out);
}

// round 2
// speedup vs baseline: 4.3334x; 4.3334x over previous
#include <cuda_runtime.h>
#include <math.h>

// ---------------- problem constants ----------------
constexpr int CB  = 4;      // batch
constexpr int CC  = 512;    // channels
constexpr int CHH = 32;     // H
constexpr int CWW = 32;     // W
constexpr int CHW = 1024;   // H*W
constexpr int CNH = 8;      // heads
constexpr int NPR = 8;      // prompt tokens
constexpr int CN  = 1032;   // total tokens
constexpr int HID = 1024;   // mlp hidden
constexpr float EPS = 1e-5f;

// ---------------- scratch (static device memory; no allocations) ----------------
__device__ __align__(16) float g_dw1 [CB*CC*CHW];
__device__ __align__(16) float g_dsf [CB*CC*CHW];
__device__ __align__(16) float g_pp1t[CB*CHW*CC];
__device__ __align__(16) float g_pp2t[CB*CHW*CC];
__device__ __align__(16) float g_ds  [CB*CHW];
__device__ __align__(16) float g_prompt[CB*NPR*CC];
__device__ __align__(16) float g_jd  [CB*CN];
__device__ __align__(16) float g_jt  [CB*CN*CC];
__device__ __align__(16) float g_x   [CB*CN*CC];
__device__ __align__(16) float g_q   [CB*CN*CC];
__device__ __align__(16) float g_k   [CB*CN*CC];
__device__ __align__(16) float g_v   [CB*CN*CC];
__device__ __align__(16) float g_ao  [CB*CN*CC];
__device__ __align__(16) float g_h   [CB*CN*HID];
__device__ __align__(16) float g_enh [CB*CC*CHW];
__device__ __align__(16) float g_o1c [CB*CC*CHW];
__device__ __align__(16) float g_o1t [CB*CHW*CC];
__device__ __align__(16) float g_o2t [CB*CHW*CC];

__device__ __forceinline__ float gelu_f(float x){
    return 0.5f * x * (1.0f + erff(x * 0.70710678118654752f));
}

__device__ __forceinline__ unsigned f2tf(float f){
    unsigned u;
    asm("cvt.rna.tf32.f32 %0, %1;" : "=r"(u) : "f"(f));
    return u;
}

__device__ __forceinline__ void mma_tf32(float& d0, float& d1, float& d2, float& d3,
                                         unsigned a0, unsigned a1, unsigned a2, unsigned a3,
                                         unsigned b0, unsigned b1)
{
    asm volatile("mma.sync.aligned.m16n8k8.row.col.f32.tf32.tf32.f32 "
                 "{%0,%1,%2,%3}, {%4,%5,%6,%7}, {%8,%9}, {%0,%1,%2,%3};"
                 : "+f"(d0), "+f"(d1), "+f"(d2), "+f"(d3)
                 : "r"(a0), "r"(a1), "r"(a2), "r"(a3), "r"(b0), "r"(b1));
}

// ---------------- depthwise 3x3 conv + BN + GELU (optionally two branches) ----------------
__global__ void k_dwconv_dual(const float* __restrict__ in,
                              const float* __restrict__ w1, const float* __restrict__ bn1,
                              float* __restrict__ out1,
                              const float* __restrict__ w2, const float* __restrict__ bn2,
                              float* __restrict__ out2)
{
    int idx = blockIdx.x * 256 + threadIdx.x;
    if (idx >= CB*CC*CHW) return;
    int p = idx & (CHW-1);
    int c = (idx >> 10) & (CC-1);
    int y = p >> 5, x = p & 31;
    const float* base = in + (size_t)(idx - p);
    float v[9];
#pragma unroll
    for (int ky = 0; ky < 3; ky++)
#pragma unroll
        for (int kx = 0; kx < 3; kx++){
            int yy = y + ky - 1, xx = x + kx - 1;
            v[ky*3+kx] = (yy >= 0 && yy < CHH && xx >= 0 && xx < CWW) ? base[yy*CWW + xx] : 0.f;
        }
    {
        float a = 0.f;
#pragma unroll
        for (int k = 0; k < 9; k++) a += w1[c*9+k] * v[k];
        float s = bn1[c] * rsqrtf(bn1[3*CC+c] + EPS);
        a = a * s + bn1[CC+c] - bn1[2*CC+c] * s;
        out1[idx] = gelu_f(a);
    }
    if (out2){
        float a = 0.f;
#pragma unroll
        for (int k = 0; k < 9; k++) a += w2[c*9+k] * v[k];
        float s = bn2[c] * rsqrtf(bn2[3*CC+c] + EPS);
        a = a * s + bn2[CC+c] - bn2[2*CC+c] * s;
        out2[idx] = gelu_f(a);
    }
}

// ---------------- transposes ----------------
__global__ void k_cp_to_tok(const float* __restrict__ in, float* __restrict__ out,
                            int tokTotal, int tokOff)
{
    __shared__ float tile[32][33];
    int b = blockIdx.z;
    int p0 = blockIdx.x * 32, c0 = blockIdx.y * 32;
    int tx = threadIdx.x, ty = threadIdx.y;
#pragma unroll
    for (int i = 0; i < 4; i++){
        int c = c0 + ty + i*8;
        tile[ty + i*8][tx] = in[((size_t)b*CC + c)*CHW + p0 + tx];
    }
    __syncthreads();
#pragma unroll
    for (int i = 0; i < 4; i++){
        int p = p0 + ty + i*8;
        out[((size_t)b*tokTotal + tokOff + p)*CC + c0 + tx] = tile[tx][ty + i*8];
    }
}

__global__ void k_tok_to_cp(const float* __restrict__ in, float* __restrict__ out,
                            int tokTotal, int tokOff)
{
    __shared__ float tile[32][33];
    int b = blockIdx.z;
    int p0 = blockIdx.x * 32, c0 = blockIdx.y * 32;
    int tx = threadIdx.x, ty = threadIdx.y;
#pragma unroll
    for (int i = 0; i < 4; i++){
        int p = p0 + ty + i*8;
        tile[ty + i*8][tx] = in[((size_t)b*tokTotal + tokOff + p)*CC + c0 + tx];
    }
    __syncthreads();
#pragma unroll
    for (int i = 0; i < 4; i++){
        int c = c0 + ty + i*8;
        out[((size_t)b*CC + c)*CHW + p0 + tx] = tile[tx][ty + i*8];
    }
}

// ---------------- tensor-core NT GEMM (tf32 mma), 128x128 tile, K-step 16 ----------------
// C[m,n] = sum_k A[m,k]*B[n,k].  EPI: 0 plain, 1 bn+gelu, 2 bias+gelu, 3 bias+res, 4 res
constexpr int GST = 20;   // padded SMEM stride (words), conflict-free for mma frag loads

template<int EPI>
__global__ void __launch_bounds__(256) k_gemm_tc(const float* __restrict__ A,
                                                 const float* __restrict__ Bw,
                                                 float* __restrict__ Cmat,
                                                 int M, int N, int K,
                                                 const float* __restrict__ ep,
                                                 const float* __restrict__ res)
{
    __shared__ unsigned As[2][128*GST];
    __shared__ unsigned Bs[2][128*GST];

    int tid  = threadIdx.x;
    int lane = tid & 31;
    int w    = tid >> 5;
    int wm   = w >> 1;         // 0..3 (M)
    int wn   = w & 1;          // 0..1 (N)
    int m0 = blockIdx.y * 128, n0 = blockIdx.x * 128;

    // load indices: 512 float4 per tile, 2 per thread
    int i0 = tid, i1 = tid + 256;
    int ar0 = i0 >> 2, ac0 = (i0 & 3) * 4;
    int ar1 = i1 >> 2, ac1 = (i1 & 3) * 4;

    float acc[2][8][4];
#pragma unroll
    for (int mf = 0; mf < 2; mf++)
#pragma unroll
        for (int nf = 0; nf < 8; nf++)
#pragma unroll
            for (int r = 0; r < 4; r++) acc[mf][nf][r] = 0.f;

    int NK = K >> 4;

    // prologue: tile 0
    {
        float4 a0 = (m0 + ar0 < M) ? *(const float4*)(A + (size_t)(m0 + ar0)*K + ac0) : make_float4(0,0,0,0);
        float4 a1 = (m0 + ar1 < M) ? *(const float4*)(A + (size_t)(m0 + ar1)*K + ac1) : make_float4(0,0,0,0);
        float4 b0 = *(const float4*)(Bw + (size_t)(n0 + ar0)*K + ac0);
        float4 b1 = *(const float4*)(Bw + (size_t)(n0 + ar1)*K + ac1);
        *(uint4*)&As[0][ar0*GST + ac0] = make_uint4(f2tf(a0.x), f2tf(a0.y), f2tf(a0.z), f2tf(a0.w));
        *(uint4*)&As[0][ar1*GST + ac1] = make_uint4(f2tf(a1.x), f2tf(a1.y), f2tf(a1.z), f2tf(a1.w));
        *(uint4*)&Bs[0][ar0*GST + ac0] = make_uint4(f2tf(b0.x), f2tf(b0.y), f2tf(b0.z), f2tf(b0.w));
        *(uint4*)&Bs[0][ar1*GST + ac1] = make_uint4(f2tf(b1.x), f2tf(b1.y), f2tf(b1.z), f2tf(b1.w));
    }
    __syncthreads();

    for (int kt = 0; kt < NK; kt++){
        float4 a0, a1, b0, b1;
        bool has_next = (kt + 1 < NK);
        if (has_next){
            int kb = (kt + 1) << 4;
            a0 = (m0 + ar0 < M) ? *(const float4*)(A + (size_t)(m0 + ar0)*K + kb + ac0) : make_float4(0,0,0,0);
            a1 = (m0 + ar1 < M) ? *(const float4*)(A + (size_t)(m0 + ar1)*K + kb + ac1) : make_float4(0,0,0,0);
            b0 = *(const float4*)(Bw + (size_t)(n0 + ar0)*K + kb + ac0);
            b1 = *(const float4*)(Bw + (size_t)(n0 + ar1)*K + kb + ac1);
        }
        const unsigned* Ac = As[kt & 1];
        const unsigned* Bc = Bs[kt & 1];
#pragma unroll
        for (int kf = 0; kf < 2; kf++){
            int kc = kf*8 + (lane & 3);
            unsigned afr[2][4];
#pragma unroll
            for (int mf = 0; mf < 2; mf++){
                int rbase = wm*32 + mf*16 + (lane >> 2);
                afr[mf][0] = Ac[(rbase    )*GST + kc    ];
                afr[mf][1] = Ac[(rbase + 8)*GST + kc    ];
                afr[mf][2] = Ac[(rbase    )*GST + kc + 4];
                afr[mf][3] = Ac[(rbase + 8)*GST + kc + 4];
            }
#pragma unroll
            for (int nf = 0; nf < 8; nf++){
                int nb = wn*64 + nf*8 + (lane >> 2);
                unsigned bb0 = Bc[nb*GST + kc];
                unsigned bb1 = Bc[nb*GST + kc + 4];
#pragma unroll
                for (int mf = 0; mf < 2; mf++)
                    mma_tf32(acc[mf][nf][0], acc[mf][nf][1], acc[mf][nf][2], acc[mf][nf][3],
                             afr[mf][0], afr[mf][1], afr[mf][2], afr[mf][3], bb0, bb1);
            }
        }
        if (has_next){
            unsigned bi = (kt + 1) & 1;
            *(uint4*)&As[bi][ar0*GST + ac0] = make_uint4(f2tf(a0.x), f2tf(a0.y), f2tf(a0.z), f2tf(a0.w));
            *(uint4*)&As[bi][ar1*GST + ac1] = make_uint4(f2tf(a1.x), f2tf(a1.y), f2tf(a1.z), f2tf(a1.w));
            *(uint4*)&Bs[bi][ar0*GST + ac0] = make_uint4(f2tf(b0.x), f2tf(b0.y), f2tf(b0.z), f2tf(b0.w));
            *(uint4*)&Bs[bi][ar1*GST + ac1] = make_uint4(f2tf(b1.x), f2tf(b1.y), f2tf(b1.z), f2tf(b1.w));
        }
        __syncthreads();
    }

    // epilogue
#pragma unroll
    for (int mf = 0; mf < 2; mf++){
#pragma unroll
        for (int ri = 0; ri < 2; ri++){
            int row = m0 + wm*32 + mf*16 + (lane >> 2) + ri*8;
            if (row >= M) continue;
            size_t base = (size_t)row * N;
#pragma unroll
            for (int nf = 0; nf < 8; nf++){
                int col = n0 + wn*64 + nf*8 + 2*(lane & 3);
                float v0 = acc[mf][nf][ri*2 + 0];
                float v1 = acc[mf][nf][ri*2 + 1];
                if (EPI == 1){
                    float s0 = ep[col]   * rsqrtf(ep[3*N+col]   + EPS);
                    float s1 = ep[col+1] * rsqrtf(ep[3*N+col+1] + EPS);
                    v0 = gelu_f(v0 * s0 + ep[N+col]   - ep[2*N+col]   * s0);
                    v1 = gelu_f(v1 * s1 + ep[N+col+1] - ep[2*N+col+1] * s1);
                } else if (EPI == 2){
                    v0 = gelu_f(v0 + ep[col]);
                    v1 = gelu_f(v1 + ep[col+1]);
                } else if (EPI == 3){
                    float2 rr = *(const float2*)(res + base + col);
                    v0 = rr.x + v0 + ep[col];
                    v1 = rr.y + v1 + ep[col+1];
                } else if (EPI == 4){
                    float2 rr = *(const float2*)(res + base + col);
                    v0 = rr.x + v0;
                    v1 = rr.y + v1;
                }
                *(float2*)(Cmat + base + col) = make_float2(v0, v1);
            }
        }
    }
}

// ---------------- geometry prior: 512->1 projection (parallel) ----------------
__global__ void k_gp_pw(const float* __restrict__ dsf, const float* __restrict__ w,
                        const float* __restrict__ bias, float* __restrict__ ds)
{
    // block: 256 threads = 32 pixels x 8 channel-chunks of 64
    __shared__ float red[8][33];
    int px = threadIdx.x & 31;
    int cz = threadIdx.x >> 5;
    int p0 = blockIdx.x * 32;
    int b  = p0 >> 10;
    int p  = (p0 & (CHW-1)) + px;
    float acc = 0.f;
#pragma unroll
    for (int i = 0; i < 64; i++){
        int c = cz*64 + i;
        acc += w[c] * dsf[((size_t)b*CC + c)*CHW + p];
    }
    red[cz][px] = acc;
    __syncthreads();
    if (cz == 0){
        float s = 0.f;
#pragma unroll
        for (int z = 0; z < 8; z++) s += red[z][px];
        ds[p0 + px] = s + bias[0];
    }
}

// ---------------- prompt: pool + embed + LN ----------------
__global__ void k_prompt(const float* __restrict__ pp2t, const float* __restrict__ pe,
                         const float* __restrict__ lnp, float* __restrict__ out)
{
    int b = blockIdx.x >> 3, pr = blockIdx.x & 7;
    int iy = pr >> 2, ix = pr & 3;
    int t = threadIdx.x;
    float a0 = 0.f, a1 = 0.f;
    for (int py = 0; py < 16; py++)
        for (int px = 0; px < 8; px++){
            int p = (iy*16 + py)*CWW + ix*8 + px;
            const float* base = pp2t + ((size_t)b*CHW + p)*CC;
            a0 += base[t];
            a1 += base[t + 256];
        }
    a0 = a0 * (1.f/128.f) + pe[pr*CC + t];
    a1 = a1 * (1.f/128.f) + pe[pr*CC + t + 256];
    __shared__ float rs[256], rq[256];
    rs[t] = a0 + a1; rq[t] = a0*a0 + a1*a1;
    __syncthreads();
    for (int s = 128; s > 0; s >>= 1){
        if (t < s){ rs[t] += rs[t+s]; rq[t] += rq[t+s]; }
        __syncthreads();
    }
    float mean = rs[0] * (1.f/512.f);
    float var  = rq[0] * (1.f/512.f) - mean*mean;
    float inv  = rsqrtf(var + EPS);
    size_t o = ((size_t)b*NPR + pr) * CC;
    out[o + t]       = (a0 - mean) * inv * lnp[t]       + lnp[CC + t];
    out[o + t + 256] = (a1 - mean) * inv * lnp[t + 256] + lnp[CC + t + 256];
}

// ---------------- joint depth scalar per token ----------------
__global__ void k_jd(const float* __restrict__ ds, float* __restrict__ jd)
{
    int t = blockIdx.x * 256 + threadIdx.x;
    if (t >= CB*CN) return;
    int b = t / CN, n = t % CN;
    if (n >= NPR){
        jd[t] = ds[b*CHW + (n - NPR)];
    } else {
        int iy = n >> 2, ix = n & 3;
        float acc = 0.f;
        for (int py = 0; py < 16; py++)
            for (int px = 0; px < 8; px++)
                acc += ds[b*CHW + (iy*16 + py)*CWW + ix*8 + px];
        jd[t] = acc * (1.f/128.f);
    }
}

// ---------------- copy prompt tokens into jt ----------------
__global__ void k_copy_prompt(const float* __restrict__ pr, float* __restrict__ jt)
{
    int idx = blockIdx.x * 256 + threadIdx.x;
    if (idx >= CB*NPR*CC) return;
    int b = idx / (NPR*CC), r = idx % (NPR*CC);
    jt[(size_t)b*CN*CC + r] = pr[(size_t)b*NPR*CC + r];
}

// ---------------- layernorm over C per token ----------------
__global__ void k_ln(const float* __restrict__ in, const float* __restrict__ p,
                     float* __restrict__ out)
{
    int tok = blockIdx.x;
    const float* row = in + (size_t)tok * CC;
    int t = threadIdx.x;
    float v0 = row[t], v1 = row[t + 256];
    __shared__ float rs[256], rq[256];
    rs[t] = v0 + v1; rq[t] = v0*v0 + v1*v1;
    __syncthreads();
    for (int s = 128; s > 0; s >>= 1){
        if (t < s){ rs[t] += rs[t+s]; rq[t] += rq[t+s]; }
        __syncthreads();
    }
    float mean = rs[0] * (1.f/512.f);
    float var  = rq[0] * (1.f/512.f) - mean*mean;
    float inv  = rsqrtf(var + EPS);
    size_t o = (size_t)tok * CC;
    out[o + t]       = (v0 - mean) * inv * p[t]       + p[CC + t];
    out[o + t + 256] = (v1 - mean) * inv * p[t + 256] + p[CC + t + 256];
}

// ---------------- attention: flash-style, tf32 mma, analytic bias ----------------
__device__ __forceinline__ void tok_coord(int n, float& cy, float& cx){
    if (n < NPR){ cy = (float)(n >> 2); cx = (float)(n & 3) * (1.f/3.f); }
    else { int m = n - NPR; cy = (float)(m >> 5) * (1.f/31.f); cx = (float)(m & 31) * (1.f/31.f); }
}

constexpr int QS_OFF = 0;                    // 128 x 68
constexpr int KS_OFF = QS_OFF + 128*68;      // 64 x 68
constexpr int VS_OFF = KS_OFF + 64*68;       // 64 x 72
constexpr int PS_OFF = VS_OFF + 64*72;       // 128 x 68
constexpr int KD_OFF = PS_OFF + 128*68;      // 64 floats
constexpr int ATTN_SMEM = (KD_OFF + 64) * 4; // bytes

__global__ void __launch_bounds__(256) k_attn(const float* __restrict__ qg,
                                              const float* __restrict__ kg,
                                              const float* __restrict__ vg,
                                              const float* __restrict__ jd,
                                              const float* __restrict__ gw,
                                              float* __restrict__ ao)
{
    extern __shared__ unsigned smu[];
    unsigned* Qs = smu + QS_OFF;
    unsigned* Ks = smu + KS_OFF;
    unsigned* Vs = smu + VS_OFF;
    unsigned* Ps = smu + PS_OFF;
    float*  kdep = (float*)(smu + KD_OFF);

    int b = blockIdx.z, h = blockIdx.y, q0 = blockIdx.x * 128;
    int tid = threadIdx.x, lane = tid & 31, w = tid >> 5;

    const float decay = logf(1.f - exp2f(-1.f - 0.5f * (float)h));
    const float w0 = gw[0] * decay, w1 = gw[1] * decay;

    // load Q tile (128 x 64), tf32, stride 68
    {
#pragma unroll
        for (int j = 0; j < 8; j++){
            int i = tid + 256*j;            // float4 index: 16 per row
            int r = i >> 4, c4 = (i & 15) * 4;
            int qn = q0 + r;
            float4 v = (qn < CN) ? *(const float4*)(qg + ((size_t)b*CN + qn)*CC + h*64 + c4)
                                 : make_float4(0,0,0,0);
            *(uint4*)&Qs[r*68 + c4] = make_uint4(f2tf(v.x), f2tf(v.y), f2tf(v.z), f2tf(v.w));
        }
    }

    // q-row metadata (2 rows per thread)
    float qy[2], qx[2], qd[2];
#pragma unroll
    for (int i = 0; i < 2; i++){
        int qn = q0 + w*16 + (lane >> 2) + i*8;
        if (qn < CN){ tok_coord(qn, qy[i], qx[i]); qd[i] = jd[b*CN + qn]; }
        else { qy[i] = qx[i] = qd[i] = 0.f; }
    }

    float O[8][4];
#pragma unroll
    for (int nf = 0; nf < 8; nf++)
#pragma unroll
        for (int r = 0; r < 4; r++) O[nf][r] = 0.f;
    float mi[2] = {-1e30f, -1e30f}, li[2] = {0.f, 0.f};

    for (int kt = 0; kt < 17; kt++){
        int k0 = kt * 64;
        __syncthreads();   // previous tile fully consumed
        // load K, V tiles (64 x 64)
#pragma unroll
        for (int j = 0; j < 4; j++){
            int i = tid + 256*j;
            int r = i >> 4, c4 = (i & 15) * 4;
            int n = k0 + r;
            bool val = (n < CN);
            float4 kv = val ? *(const float4*)(kg + ((size_t)b*CN + n)*CC + h*64 + c4) : make_float4(0,0,0,0);
            float4 vv = val ? *(const float4*)(vg + ((size_t)b*CN + n)*CC + h*64 + c4) : make_float4(0,0,0,0);
            *(uint4*)&Ks[r*68 + c4] = make_uint4(f2tf(kv.x), f2tf(kv.y), f2tf(kv.z), f2tf(kv.w));
            *(uint4*)&Vs[r*72 + c4] = make_uint4(f2tf(vv.x), f2tf(vv.y), f2tf(vv.z), f2tf(vv.w));
        }
        if (tid < 64) kdep[tid] = (k0 + tid < CN) ? jd[b*CN + k0 + tid] : 0.f;
        __syncthreads();

        // S = Q K^T (warp computes its 16 rows x 64 cols)
        float S[8][4];
#pragma unroll
        for (int nf = 0; nf < 8; nf++)
#pragma unroll
            for (int r = 0; r < 4; r++) S[nf][r] = 0.f;
#pragma unroll
        for (int kf = 0; kf < 8; kf++){
            int kc = kf*8 + (lane & 3);
            int rbase = w*16 + (lane >> 2);
            unsigned a0 = Qs[(rbase    )*68 + kc    ];
            unsigned a1 = Qs[(rbase + 8)*68 + kc    ];
            unsigned a2 = Qs[(rbase    )*68 + kc + 4];
            unsigned a3 = Qs[(rbase + 8)*68 + kc + 4];
#pragma unroll
            for (int nf = 0; nf < 8; nf++){
                int nb = nf*8 + (lane >> 2);
                unsigned b0 = Ks[nb*68 + kc];
                unsigned b1 = Ks[nb*68 + kc + 4];
                mma_tf32(S[nf][0], S[nf][1], S[nf][2], S[nf][3], a0, a1, a2, a3, b0, b1);
            }
        }

        // bias + scale, validity
        bool kval[8][2];
#pragma unroll
        for (int nf = 0; nf < 8; nf++){
#pragma unroll
            for (int j = 0; j < 2; j++){
                int kl = nf*8 + (lane & 3)*2 + j;
                int kn = k0 + kl;
                kval[nf][j] = (kn < CN);
                float ky, kx;
                tok_coord(kn, ky, kx);
                float kd = kdep[kl];
#pragma unroll
                for (int i = 0; i < 2; i++){
                    float pos = fabsf(qy[i]-ky) + fabsf(qx[i]-kx);
                    float vv = S[nf][i*2+j]*0.125f + w0*pos + w1*fabsf(qd[i]-kd);
                    S[nf][i*2+j] = kval[nf][j] ? vv : -1e30f;
                }
            }
        }

        // online softmax per row (quad reduction)
        float alpha[2];
#pragma unroll
        for (int i = 0; i < 2; i++){
            float tm = -1e30f;
#pragma unroll
            for (int nf = 0; nf < 8; nf++){
                tm = fmaxf(tm, S[nf][i*2]);
                tm = fmaxf(tm, S[nf][i*2+1]);
            }
            tm = fmaxf(tm, __shfl_xor_sync(0xffffffffu, tm, 1));
            tm = fmaxf(tm, __shfl_xor_sync(0xffffffffu, tm, 2));
            float mn = fmaxf(mi[i], tm);
            alpha[i] = __expf(mi[i] - mn);
            float ssum = 0.f;
#pragma unroll
            for (int nf = 0; nf < 8; nf++){
#pragma unroll
                for (int j = 0; j < 2; j++){
                    float p = kval[nf][j] ? __expf(S[nf][i*2+j] - mn) : 0.f;
                    S[nf][i*2+j] = p;
                    ssum += p;
                }
            }
            ssum += __shfl_xor_sync(0xffffffffu, ssum, 1);
            ssum += __shfl_xor_sync(0xffffffffu, ssum, 2);
            li[i] = li[i]*alpha[i] + ssum;
            mi[i] = mn;
        }
        // rescale O
#pragma unroll
        for (int nf = 0; nf < 8; nf++){
            O[nf][0] *= alpha[0]; O[nf][1] *= alpha[0];
            O[nf][2] *= alpha[1]; O[nf][3] *= alpha[1];
        }
        // write P to smem (warp-private rows)
#pragma unroll
        for (int nf = 0; nf < 8; nf++){
#pragma unroll
            for (int i = 0; i < 2; i++){
                int r = w*16 + (lane >> 2) + i*8;
                int c = nf*8 + (lane & 3)*2;
                Ps[r*68 + c]     = f2tf(S[nf][i*2]);
                Ps[r*68 + c + 1] = f2tf(S[nf][i*2+1]);
            }
        }
        __syncwarp();

        // O += P V
#pragma unroll
        for (int kf = 0; kf < 8; kf++){
            int kc = kf*8 + (lane & 3);
            int rbase = w*16 + (lane >> 2);
            unsigned a0 = Ps[(rbase    )*68 + kc    ];
            unsigned a1 = Ps[(rbase + 8)*68 + kc    ];
            unsigned a2 = Ps[(rbase    )*68 + kc + 4];
            unsigned a3 = Ps[(rbase + 8)*68 + kc + 4];
#pragma unroll
            for (int nf = 0; nf < 8; nf++){
                unsigned b0 = Vs[(kf*8 + (lane & 3)    )*72 + nf*8 + (lane >> 2)];
                unsigned b1 = Vs[(kf*8 + (lane & 3) + 4)*72 + nf*8 + (lane >> 2)];
                mma_tf32(O[nf][0], O[nf][1], O[nf][2], O[nf][3], a0, a1, a2, a3, b0, b1);
            }
        }
    }

    // epilogue
#pragma unroll
    for (int i = 0; i < 2; i++){
        int qn = q0 + w*16 + (lane >> 2) + i*8;
        if (qn >= CN) continue;
        float invl = 1.f / li[i];
        size_t base = ((size_t)b*CN + qn)*CC + h*64;
#pragma unroll
        for (int nf = 0; nf < 8; nf++){
            int c = nf*8 + (lane & 3)*2;
            *(float2*)(ao + base + c) = make_float2(O[nf][i*2]*invl, O[nf][i*2+1]*invl);
        }
    }
}

// ---------------- final: out = fused + BN(op_pw output), with transpose ----------------
__global__ void k_final(const float* __restrict__ fused, const float* __restrict__ o2t,
                        const float* __restrict__ bn, float* __restrict__ out)
{
    __shared__ float tile[32][33];
    int b = blockIdx.z;
    int p0 = blockIdx.x * 32, c0 = blockIdx.y * 32;
    int tx = threadIdx.x, ty = threadIdx.y;
#pragma unroll
    for (int i = 0; i < 4; i++){
        int p = p0 + ty + i*8;
        tile[ty + i*8][tx] = o2t[((size_t)b*CHW + p)*CC + c0 + tx];
    }
    __syncthreads();
#pragma unroll
    for (int i = 0; i < 4; i++){
        int c = c0 + ty + i*8;
        float s = bn[c] * rsqrtf(bn[3*CC+c] + EPS);
        float t = bn[CC+c] - bn[2*CC+c] * s;
        size_t idx = ((size_t)b*CC + c)*CHW + p0 + tx;
        out[idx] = fused[idx] + tile[tx][ty + i*8] * s + t;
    }
}

// ---------------- host ----------------
static void launch_gemm(int epi, const float* A, const float* Bw, float* Cm,
                        int M, int N, int K, const float* ep, const float* res)
{
    dim3 g(N/128, (M + 127)/128);
    switch (epi){
        case 0: k_gemm_tc<0><<<g,256>>>(A,Bw,Cm,M,N,K,ep,res); break;
        case 1: k_gemm_tc<1><<<g,256>>>(A,Bw,Cm,M,N,K,ep,res); break;
        case 2: k_gemm_tc<2><<<g,256>>>(A,Bw,Cm,M,N,K,ep,res); break;
        case 3: k_gemm_tc<3><<<g,256>>>(A,Bw,Cm,M,N,K,ep,res); break;
        case 4: k_gemm_tc<4><<<g,256>>>(A,Bw,Cm,M,N,K,ep,res); break;
    }
}

extern "C" void kernel_launch(void* const* d_in, const int* in_sizes, int n_in,
                              void* d_out, int out_size)
{
    const float* fused        = (const float*)d_in[0];
    const float* depth        = (const float*)d_in[1];
    const float* pg_dw_w      = (const float*)d_in[2];
    const float* pg_bn1       = (const float*)d_in[3];
    const float* pg_pw_w      = (const float*)d_in[4];
    const float* pg_bn2       = (const float*)d_in[5];
    const float* prompt_embed = (const float*)d_in[6];
    const float* pg_ln        = (const float*)d_in[7];
    const float* gp_dw_w      = (const float*)d_in[8];
    const float* gp_bn        = (const float*)d_in[9];
    const float* gp_pw_w      = (const float*)d_in[10];
    const float* gp_pw_b      = (const float*)d_in[11];
    const float* gp_weight    = (const float*)d_in[12];
    const float* ln1          = (const float*)d_in[13];
    const float* wq           = (const float*)d_in[14];
    const float* wk           = (const float*)d_in[15];
    const float* wv           = (const float*)d_in[16];
    const float* wo           = (const float*)d_in[17];
    const float* ln2          = (const float*)d_in[18];
    const float* mlp_w1       = (const float*)d_in[19];
    const float* mlp_b1       = (const float*)d_in[20];
    const float* mlp_w2       = (const float*)d_in[21];
    const float* mlp_b2       = (const float*)d_in[22];
    const float* op_dw_w      = (const float*)d_in[23];
    const float* op_bn1       = (const float*)d_in[24];
    const float* op_pw_w      = (const float*)d_in[25];
    const float* op_bn2       = (const float*)d_in[26];

    float *dw1,*dsf,*pp1t,*pp2t,*ds,*prm,*jdb,*jt,*xb,*qb,*kb,*vb,*aob,*hb,*enh,*o1c,*o1t,*o2t;
    cudaGetSymbolAddress((void**)&dw1,  g_dw1);
    cudaGetSymbolAddress((void**)&dsf,  g_dsf);
    cudaGetSymbolAddress((void**)&pp1t, g_pp1t);
    cudaGetSymbolAddress((void**)&pp2t, g_pp2t);
    cudaGetSymbolAddress((void**)&ds,   g_ds);
    cudaGetSymbolAddress((void**)&prm,  g_prompt);
    cudaGetSymbolAddress((void**)&jdb,  g_jd);
    cudaGetSymbolAddress((void**)&jt,   g_jt);
    cudaGetSymbolAddress((void**)&xb,   g_x);
    cudaGetSymbolAddress((void**)&qb,   g_q);
    cudaGetSymbolAddress((void**)&kb,   g_k);
    cudaGetSymbolAddress((void**)&vb,   g_v);
    cudaGetSymbolAddress((void**)&aob,  g_ao);
    cudaGetSymbolAddress((void**)&hb,   g_h);
    cudaGetSymbolAddress((void**)&enh,  g_enh);
    cudaGetSymbolAddress((void**)&o1c,  g_o1c);
    cudaGetSymbolAddress((void**)&o1t,  g_o1t);
    cudaGetSymbolAddress((void**)&o2t,  g_o2t);

    cudaFuncSetAttribute(k_attn, cudaFuncAttributeMaxDynamicSharedMemorySize, ATTN_SMEM);

    dim3 tgrid(CHW/32, CC/32, CB), tblk(32, 8);

    // --- DepthPromptGenerator + GeometryPriorGenerator shared dwconv ---
    k_dwconv_dual<<<(CB*CC*CHW)/256, 256>>>(depth, pg_dw_w, pg_bn1, dw1, gp_dw_w, gp_bn, dsf);
    k_cp_to_tok<<<tgrid, tblk>>>(dw1, pp1t, CHW, 0);
    launch_gemm(1, pp1t, pg_pw_w, pp2t, CB*CHW, CC, CC, pg_bn2, nullptr);   // bn2 + gelu
    k_gp_pw<<<(CB*CHW)/32, 256>>>(dsf, gp_pw_w, gp_pw_b, ds);
    k_prompt<<<CB*NPR, 256>>>(pp2t, prompt_embed, pg_ln, prm);
    k_jd<<<(CB*CN + 255)/256, 256>>>(ds, jdb);

    // --- assemble joint tokens ---
    k_copy_prompt<<<(CB*NPR*CC)/256, 256>>>(prm, jt);
    k_cp_to_tok<<<tgrid, tblk>>>(fused, jt, CN, NPR);

    // --- attention block ---
    k_ln<<<CB*CN, 256>>>(jt, ln1, xb);
    launch_gemm(0, xb, wq, qb, CB*CN, CC, CC, nullptr, nullptr);
    launch_gemm(0, xb, wk, kb, CB*CN, CC, CC, nullptr, nullptr);
    launch_gemm(0, xb, wv, vb, CB*CN, CC, CC, nullptr, nullptr);
    k_attn<<<dim3(9, CNH, CB), 256, ATTN_SMEM>>>(qb, kb, vb, jdb, gp_weight, aob);
    launch_gemm(4, aob, wo, jt, CB*CN, CC, CC, nullptr, jt);                // jt += ao@wo^T

    // --- MLP ---
    k_ln<<<CB*CN, 256>>>(jt, ln2, xb);
    launch_gemm(2, xb, mlp_w1, hb, CB*CN, HID, CC, mlp_b1, nullptr);        // bias + gelu
    launch_gemm(3, hb, mlp_w2, jt, CB*CN, CC, HID, mlp_b2, jt);             // bias + residual

    // --- out_proj ---
    k_tok_to_cp<<<tgrid, tblk>>>(jt, enh, CN, NPR);
    k_dwconv_dual<<<(CB*CC*CHW)/256, 256>>>(enh, op_dw_w, op_bn1, o1c, nullptr, nullptr, nullptr);
    k_cp_to_tok<<<tgrid, tblk>>>(o1c, o1t, CHW, 0);
    launch_gemm(0, o1t, op_pw_w, o2t, CB*CHW, CC, CC, nullptr, nullptr);
    k_final<<<tgrid, tblk>>>(fused, o2t, op_bn2, (float*)d_out);
}

// round 3
// speedup vs baseline: 4.3711x; 1.0087x over previous
#include <cuda_runtime.h>
#include <math.h>

// ---------------- problem constants ----------------
constexpr int CB  = 4;      // batch
constexpr int CC  = 512;    // channels
constexpr int CHH = 32;     // H
constexpr int CWW = 32;     // W
constexpr int CHW = 1024;   // H*W
constexpr int CNH = 8;      // heads
constexpr int NPR = 8;      // prompt tokens
constexpr int CN  = 1032;   // total tokens
constexpr int HID = 1024;   // mlp hidden
constexpr float EPS = 1e-5f;

// ---------------- scratch (static device memory; no allocations) ----------------
__device__ __align__(16) float g_dw1 [CB*CC*CHW];
__device__ __align__(16) float g_dsf [CB*CC*CHW];
__device__ __align__(16) float g_pp1t[CB*CHW*CC];
__device__ __align__(16) float g_pp2t[CB*CHW*CC];
__device__ __align__(16) float g_ds  [CB*CHW];
__device__ __align__(16) float g_prompt[CB*NPR*CC];
__device__ __align__(16) float g_jd  [CB*CN];
__device__ __align__(16) float g_jt  [CB*CN*CC];
__device__ __align__(16) float g_x   [CB*CN*CC];
__device__ __align__(16) float g_q   [CB*CN*CC];
__device__ __align__(16) float g_k   [CB*CN*CC];
__device__ __align__(16) float g_v   [CB*CN*CC];
__device__ __align__(16) float g_ao  [CB*CN*CC];
__device__ __align__(16) float g_h   [CB*CN*HID];
__device__ __align__(16) float g_enh [CB*CC*CHW];
__device__ __align__(16) float g_o1c [CB*CC*CHW];
__device__ __align__(16) float g_o1t [CB*CHW*CC];
__device__ __align__(16) float g_o2t [CB*CHW*CC];

__device__ __forceinline__ float gelu_f(float x){
    return 0.5f * x * (1.0f + erff(x * 0.70710678118654752f));
}

__device__ __forceinline__ unsigned f2tf(float f){
    unsigned u;
    asm("cvt.rna.tf32.f32 %0, %1;" : "=r"(u) : "f"(f));
    return u;
}

__device__ __forceinline__ void mma_tf32(float& d0, float& d1, float& d2, float& d3,
                                         unsigned a0, unsigned a1, unsigned a2, unsigned a3,
                                         unsigned b0, unsigned b1)
{
    asm volatile("mma.sync.aligned.m16n8k8.row.col.f32.tf32.tf32.f32 "
                 "{%0,%1,%2,%3}, {%4,%5,%6,%7}, {%8,%9}, {%0,%1,%2,%3};"
                 : "+f"(d0), "+f"(d1), "+f"(d2), "+f"(d3)
                 : "r"(a0), "r"(a1), "r"(a2), "r"(a3), "r"(b0), "r"(b1));
}

// ---------------- depthwise 3x3 conv + BN + GELU (optionally two branches) ----------------
__global__ void k_dwconv_dual(const float* __restrict__ in,
                              const float* __restrict__ w1, const float* __restrict__ bn1,
                              float* __restrict__ out1,
                              const float* __restrict__ w2, const float* __restrict__ bn2,
                              float* __restrict__ out2)
{
    int idx = blockIdx.x * 256 + threadIdx.x;
    if (idx >= CB*CC*CHW) return;
    int p = idx & (CHW-1);
    int c = (idx >> 10) & (CC-1);
    int y = p >> 5, x = p & 31;
    const float* base = in + (size_t)(idx - p);
    float v[9];
#pragma unroll
    for (int ky = 0; ky < 3; ky++)
#pragma unroll
        for (int kx = 0; kx < 3; kx++){
            int yy = y + ky - 1, xx = x + kx - 1;
            v[ky*3+kx] = (yy >= 0 && yy < CHH && xx >= 0 && xx < CWW) ? base[yy*CWW + xx] : 0.f;
        }
    {
        float a = 0.f;
#pragma unroll
        for (int k = 0; k < 9; k++) a += w1[c*9+k] * v[k];
        float s = bn1[c] * rsqrtf(bn1[3*CC+c] + EPS);
        a = a * s + bn1[CC+c] - bn1[2*CC+c] * s;
        out1[idx] = gelu_f(a);
    }
    if (out2){
        float a = 0.f;
#pragma unroll
        for (int k = 0; k < 9; k++) a += w2[c*9+k] * v[k];
        float s = bn2[c] * rsqrtf(bn2[3*CC+c] + EPS);
        a = a * s + bn2[CC+c] - bn2[2*CC+c] * s;
        out2[idx] = gelu_f(a);
    }
}

// ---------------- transposes ----------------
__global__ void k_cp_to_tok(const float* __restrict__ in, float* __restrict__ out,
                            int tokTotal, int tokOff)
{
    __shared__ float tile[32][33];
    int b = blockIdx.z;
    int p0 = blockIdx.x * 32, c0 = blockIdx.y * 32;
    int tx = threadIdx.x, ty = threadIdx.y;
#pragma unroll
    for (int i = 0; i < 4; i++){
        int c = c0 + ty + i*8;
        tile[ty + i*8][tx] = in[((size_t)b*CC + c)*CHW + p0 + tx];
    }
    __syncthreads();
#pragma unroll
    for (int i = 0; i < 4; i++){
        int p = p0 + ty + i*8;
        out[((size_t)b*tokTotal + tokOff + p)*CC + c0 + tx] = tile[tx][ty + i*8];
    }
}

__global__ void k_tok_to_cp(const float* __restrict__ in, float* __restrict__ out,
                            int tokTotal, int tokOff)
{
    __shared__ float tile[32][33];
    int b = blockIdx.z;
    int p0 = blockIdx.x * 32, c0 = blockIdx.y * 32;
    int tx = threadIdx.x, ty = threadIdx.y;
#pragma unroll
    for (int i = 0; i < 4; i++){
        int p = p0 + ty + i*8;
        tile[ty + i*8][tx] = in[((size_t)b*tokTotal + tokOff + p)*CC + c0 + tx];
    }
    __syncthreads();
#pragma unroll
    for (int i = 0; i < 4; i++){
        int c = c0 + ty + i*8;
        out[((size_t)b*CC + c)*CHW + p0 + tx] = tile[tx][ty + i*8];
    }
}

// ---------------- tensor-core NT GEMM (tf32 mma), 128x128 tile, K-step 16 ----------------
// C[m,n] = sum_k A[m,k]*B[n,k].  EPI: 0 plain, 1 bn+gelu, 2 bias+gelu, 3 bias+res, 4 res
constexpr int GST = 20;   // padded SMEM stride (words), conflict-free for mma frag loads

template<int EPI>
__global__ void __launch_bounds__(256) k_gemm_tc(const float* __restrict__ A,
                                                 const float* __restrict__ Bw,
                                                 float* __restrict__ Cmat,
                                                 int M, int N, int K,
                                                 const float* __restrict__ ep,
                                                 const float* __restrict__ res)
{
    __shared__ unsigned As[2][128*GST];
    __shared__ unsigned Bs[2][128*GST];

    int tid  = threadIdx.x;
    int lane = tid & 31;
    int w    = tid >> 5;
    int wm   = w >> 1;         // 0..3 (M)
    int wn   = w & 1;          // 0..1 (N)
    int m0 = blockIdx.y * 128, n0 = blockIdx.x * 128;

    // load indices: 512 float4 per tile, 2 per thread
    int i0 = tid, i1 = tid + 256;
    int ar0 = i0 >> 2, ac0 = (i0 & 3) * 4;
    int ar1 = i1 >> 2, ac1 = (i1 & 3) * 4;

    float acc[2][8][4];
#pragma unroll
    for (int mf = 0; mf < 2; mf++)
#pragma unroll
        for (int nf = 0; nf < 8; nf++)
#pragma unroll
            for (int r = 0; r < 4; r++) acc[mf][nf][r] = 0.f;

    int NK = K >> 4;

    // prologue: tile 0
    {
        float4 a0 = (m0 + ar0 < M) ? *(const float4*)(A + (size_t)(m0 + ar0)*K + ac0) : make_float4(0,0,0,0);
        float4 a1 = (m0 + ar1 < M) ? *(const float4*)(A + (size_t)(m0 + ar1)*K + ac1) : make_float4(0,0,0,0);
        float4 b0 = *(const float4*)(Bw + (size_t)(n0 + ar0)*K + ac0);
        float4 b1 = *(const float4*)(Bw + (size_t)(n0 + ar1)*K + ac1);
        *(uint4*)&As[0][ar0*GST + ac0] = make_uint4(f2tf(a0.x), f2tf(a0.y), f2tf(a0.z), f2tf(a0.w));
        *(uint4*)&As[0][ar1*GST + ac1] = make_uint4(f2tf(a1.x), f2tf(a1.y), f2tf(a1.z), f2tf(a1.w));
        *(uint4*)&Bs[0][ar0*GST + ac0] = make_uint4(f2tf(b0.x), f2tf(b0.y), f2tf(b0.z), f2tf(b0.w));
        *(uint4*)&Bs[0][ar1*GST + ac1] = make_uint4(f2tf(b1.x), f2tf(b1.y), f2tf(b1.z), f2tf(b1.w));
    }
    __syncthreads();

    for (int kt = 0; kt < NK; kt++){
        float4 a0, a1, b0, b1;
        bool has_next = (kt + 1 < NK);
        if (has_next){
            int kb = (kt + 1) << 4;
            a0 = (m0 + ar0 < M) ? *(const float4*)(A + (size_t)(m0 + ar0)*K + kb + ac0) : make_float4(0,0,0,0);
            a1 = (m0 + ar1 < M) ? *(const float4*)(A + (size_t)(m0 + ar1)*K + kb + ac1) : make_float4(0,0,0,0);
            b0 = *(const float4*)(Bw + (size_t)(n0 + ar0)*K + kb + ac0);
            b1 = *(const float4*)(Bw + (size_t)(n0 + ar1)*K + kb + ac1);
        }
        const unsigned* Ac = As[kt & 1];
        const unsigned* Bc = Bs[kt & 1];
#pragma unroll
        for (int kf = 0; kf < 2; kf++){
            int kc = kf*8 + (lane & 3);
            unsigned afr[2][4];
#pragma unroll
            for (int mf = 0; mf < 2; mf++){
                int rbase = wm*32 + mf*16 + (lane >> 2);
                afr[mf][0] = Ac[(rbase    )*GST + kc    ];
                afr[mf][1] = Ac[(rbase + 8)*GST + kc    ];
                afr[mf][2] = Ac[(rbase    )*GST + kc + 4];
                afr[mf][3] = Ac[(rbase + 8)*GST + kc + 4];
            }
#pragma unroll
            for (int nf = 0; nf < 8; nf++){
                int nb = wn*64 + nf*8 + (lane >> 2);
                unsigned bb0 = Bc[nb*GST + kc];
                unsigned bb1 = Bc[nb*GST + kc + 4];
#pragma unroll
                for (int mf = 0; mf < 2; mf++)
                    mma_tf32(acc[mf][nf][0], acc[mf][nf][1], acc[mf][nf][2], acc[mf][nf][3],
                             afr[mf][0], afr[mf][1], afr[mf][2], afr[mf][3], bb0, bb1);
            }
        }
        if (has_next){
            unsigned bi = (kt + 1) & 1;
            *(uint4*)&As[bi][ar0*GST + ac0] = make_uint4(f2tf(a0.x), f2tf(a0.y), f2tf(a0.z), f2tf(a0.w));
            *(uint4*)&As[bi][ar1*GST + ac1] = make_uint4(f2tf(a1.x), f2tf(a1.y), f2tf(a1.z), f2tf(a1.w));
            *(uint4*)&Bs[bi][ar0*GST + ac0] = make_uint4(f2tf(b0.x), f2tf(b0.y), f2tf(b0.z), f2tf(b0.w));
            *(uint4*)&Bs[bi][ar1*GST + ac1] = make_uint4(f2tf(b1.x), f2tf(b1.y), f2tf(b1.z), f2tf(b1.w));
        }
        __syncthreads();
    }

    // epilogue
#pragma unroll
    for (int mf = 0; mf < 2; mf++){
#pragma unroll
        for (int ri = 0; ri < 2; ri++){
            int row = m0 + wm*32 + mf*16 + (lane >> 2) + ri*8;
            if (row >= M) continue;
            size_t base = (size_t)row * N;
#pragma unroll
            for (int nf = 0; nf < 8; nf++){
                int col = n0 + wn*64 + nf*8 + 2*(lane & 3);
                float v0 = acc[mf][nf][ri*2 + 0];
                float v1 = acc[mf][nf][ri*2 + 1];
                if (EPI == 1){
                    float s0 = ep[col]   * rsqrtf(ep[3*N+col]   + EPS);
                    float s1 = ep[col+1] * rsqrtf(ep[3*N+col+1] + EPS);
                    v0 = gelu_f(v0 * s0 + ep[N+col]   - ep[2*N+col]   * s0);
                    v1 = gelu_f(v1 * s1 + ep[N+col+1] - ep[2*N+col+1] * s1);
                } else if (EPI == 2){
                    v0 = gelu_f(v0 + ep[col]);
                    v1 = gelu_f(v1 + ep[col+1]);
                } else if (EPI == 3){
                    float2 rr = *(const float2*)(res + base + col);
                    v0 = rr.x + v0 + ep[col];
                    v1 = rr.y + v1 + ep[col+1];
                } else if (EPI == 4){
                    float2 rr = *(const float2*)(res + base + col);
                    v0 = rr.x + v0;
                    v1 = rr.y + v1;
                }
                *(float2*)(Cmat + base + col) = make_float2(v0, v1);
            }
        }
    }
}

// ---------------- geometry prior: 512->1 projection (parallel) ----------------
__global__ void k_gp_pw(const float* __restrict__ dsf, const float* __restrict__ w,
                        const float* __restrict__ bias, float* __restrict__ ds)
{
    // block: 256 threads = 32 pixels x 8 channel-chunks of 64
    __shared__ float red[8][33];
    int px = threadIdx.x & 31;
    int cz = threadIdx.x >> 5;
    int p0 = blockIdx.x * 32;
    int b  = p0 >> 10;
    int p  = (p0 & (CHW-1)) + px;
    float acc = 0.f;
#pragma unroll
    for (int i = 0; i < 64; i++){
        int c = cz*64 + i;
        acc += w[c] * dsf[((size_t)b*CC + c)*CHW + p];
    }
    red[cz][px] = acc;
    __syncthreads();
    if (cz == 0){
        float s = 0.f;
#pragma unroll
        for (int z = 0; z < 8; z++) s += red[z][px];
        ds[p0 + px] = s + bias[0];
    }
}

// ---------------- prompt: pool + embed + LN ----------------
__global__ void k_prompt(const float* __restrict__ pp2t, const float* __restrict__ pe,
                         const float* __restrict__ lnp, float* __restrict__ out)
{
    int b = blockIdx.x >> 3, pr = blockIdx.x & 7;
    int iy = pr >> 2, ix = pr & 3;
    int t = threadIdx.x;
    float a0 = 0.f, a1 = 0.f;
    for (int py = 0; py < 16; py++)
        for (int px = 0; px < 8; px++){
            int p = (iy*16 + py)*CWW + ix*8 + px;
            const float* base = pp2t + ((size_t)b*CHW + p)*CC;
            a0 += base[t];
            a1 += base[t + 256];
        }
    a0 = a0 * (1.f/128.f) + pe[pr*CC + t];
    a1 = a1 * (1.f/128.f) + pe[pr*CC + t + 256];
    __shared__ float rs[256], rq[256];
    rs[t] = a0 + a1; rq[t] = a0*a0 + a1*a1;
    __syncthreads();
    for (int s = 128; s > 0; s >>= 1){
        if (t < s){ rs[t] += rs[t+s]; rq[t] += rq[t+s]; }
        __syncthreads();
    }
    float mean = rs[0] * (1.f/512.f);
    float var  = rq[0] * (1.f/512.f) - mean*mean;
    float inv  = rsqrtf(var + EPS);
    size_t o = ((size_t)b*NPR + pr) * CC;
    out[o + t]       = (a0 - mean) * inv * lnp[t]       + lnp[CC + t];
    out[o + t + 256] = (a1 - mean) * inv * lnp[t + 256] + lnp[CC + t + 256];
}

// ---------------- joint depth scalar per token ----------------
__global__ void k_jd(const float* __restrict__ ds, float* __restrict__ jd)
{
    int t = blockIdx.x * 256 + threadIdx.x;
    if (t >= CB*CN) return;
    int b = t / CN, n = t % CN;
    if (n >= NPR){
        jd[t] = ds[b*CHW + (n - NPR)];
    } else {
        int iy = n >> 2, ix = n & 3;
        float acc = 0.f;
        for (int py = 0; py < 16; py++)
            for (int px = 0; px < 8; px++)
                acc += ds[b*CHW + (iy*16 + py)*CWW + ix*8 + px];
        jd[t] = acc * (1.f/128.f);
    }
}

// ---------------- copy prompt tokens into jt ----------------
__global__ void k_copy_prompt(const float* __restrict__ pr, float* __restrict__ jt)
{
    int idx = blockIdx.x * 256 + threadIdx.x;
    if (idx >= CB*NPR*CC) return;
    int b = idx / (NPR*CC), r = idx % (NPR*CC);
    jt[(size_t)b*CN*CC + r] = pr[(size_t)b*NPR*CC + r];
}

// ---------------- layernorm over C per token ----------------
__global__ void k_ln(const float* __restrict__ in, const float* __restrict__ p,
                     float* __restrict__ out)
{
    int tok = blockIdx.x;
    const float* row = in + (size_t)tok * CC;
    int t = threadIdx.x;
    float v0 = row[t], v1 = row[t + 256];
    __shared__ float rs[256], rq[256];
    rs[t] = v0 + v1; rq[t] = v0*v0 + v1*v1;
    __syncthreads();
    for (int s = 128; s > 0; s >>= 1){
        if (t < s){ rs[t] += rs[t+s]; rq[t] += rq[t+s]; }
        __syncthreads();
    }
    float mean = rs[0] * (1.f/512.f);
    float var  = rq[0] * (1.f/512.f) - mean*mean;
    float inv  = rsqrtf(var + EPS);
    size_t o = (size_t)tok * CC;
    out[o + t]       = (v0 - mean) * inv * p[t]       + p[CC + t];
    out[o + t + 256] = (v1 - mean) * inv * p[t + 256] + p[CC + t + 256];
}

// ---------------- attention: flash-style, tf32 mma, analytic bias ----------------
__device__ __forceinline__ void tok_coord(int n, float& cy, float& cx){
    if (n < NPR){ cy = (float)(n >> 2); cx = (float)(n & 3) * (1.f/3.f); }
    else { int m = n - NPR; cy = (float)(m >> 5) * (1.f/31.f); cx = (float)(m & 31) * (1.f/31.f); }
}

constexpr int QS_OFF = 0;                    // 128 x 68
constexpr int KS_OFF = QS_OFF + 128*68;      // 64 x 68
constexpr int VS_OFF = KS_OFF + 64*68;       // 64 x 72
constexpr int PS_OFF = VS_OFF + 64*72;       // 128 x 68
constexpr int KD_OFF = PS_OFF + 128*68;      // 64 floats
constexpr int ATTN_SMEM = (KD_OFF + 64) * 4; // bytes

__global__ void __launch_bounds__(256) k_attn(const float* __restrict__ qg,
                                              const float* __restrict__ kg,
                                              const float* __restrict__ vg,
                                              const float* __restrict__ jd,
                                              const float* __restrict__ gw,
                                              float* __restrict__ ao)
{
    extern __shared__ unsigned smu[];
    unsigned* Qs = smu + QS_OFF;
    unsigned* Ks = smu + KS_OFF;
    unsigned* Vs = smu + VS_OFF;
    unsigned* Ps = smu + PS_OFF;
    float*  kdep = (float*)(smu + KD_OFF);

    int b = blockIdx.z, h = blockIdx.y, q0 = blockIdx.x * 128;
    int tid = threadIdx.x, lane = tid & 31, w = tid >> 5;

    const float decay = logf(1.f - exp2f(-1.f - 0.5f * (float)h));
    const float w0 = gw[0] * decay, w1 = gw[1] * decay;

    // load Q tile (128 x 64), tf32, stride 68
    {
#pragma unroll
        for (int j = 0; j < 8; j++){
            int i = tid + 256*j;            // float4 index: 16 per row
            int r = i >> 4, c4 = (i & 15) * 4;
            int qn = q0 + r;
            float4 v = (qn < CN) ? *(const float4*)(qg + ((size_t)b*CN + qn)*CC + h*64 + c4)
                                 : make_float4(0,0,0,0);
            *(uint4*)&Qs[r*68 + c4] = make_uint4(f2tf(v.x), f2tf(v.y), f2tf(v.z), f2tf(v.w));
        }
    }

    // q-row metadata (2 rows per thread)
    float qy[2], qx[2], qd[2];
#pragma unroll
    for (int i = 0; i < 2; i++){
        int qn = q0 + w*16 + (lane >> 2) + i*8;
        if (qn < CN){ tok_coord(qn, qy[i], qx[i]); qd[i] = jd[b*CN + qn]; }
        else { qy[i] = qx[i] = qd[i] = 0.f; }
    }

    float O[8][4];
#pragma unroll
    for (int nf = 0; nf < 8; nf++)
#pragma unroll
        for (int r = 0; r < 4; r++) O[nf][r] = 0.f;
    float mi[2] = {-1e30f, -1e30f}, li[2] = {0.f, 0.f};

    for (int kt = 0; kt < 17; kt++){
        int k0 = kt * 64;
        __syncthreads();   // previous tile fully consumed
        // load K, V tiles (64 x 64)
#pragma unroll
        for (int j = 0; j < 4; j++){
            int i = tid + 256*j;
            int r = i >> 4, c4 = (i & 15) * 4;
            int n = k0 + r;
            bool val = (n < CN);
            float4 kv = val ? *(const float4*)(kg + ((size_t)b*CN + n)*CC + h*64 + c4) : make_float4(0,0,0,0);
            float4 vv = val ? *(const float4*)(vg + ((size_t)b*CN + n)*CC + h*64 + c4) : make_float4(0,0,0,0);
            *(uint4*)&Ks[r*68 + c4] = make_uint4(f2tf(kv.x), f2tf(kv.y), f2tf(kv.z), f2tf(kv.w));
            *(uint4*)&Vs[r*72 + c4] = make_uint4(f2tf(vv.x), f2tf(vv.y), f2tf(vv.z), f2tf(vv.w));
        }
        if (tid < 64) kdep[tid] = (k0 + tid < CN) ? jd[b*CN + k0 + tid] : 0.f;
        __syncthreads();

        // S = Q K^T (warp computes its 16 rows x 64 cols)
        float S[8][4];
#pragma unroll
        for (int nf = 0; nf < 8; nf++)
#pragma unroll
            for (int r = 0; r < 4; r++) S[nf][r] = 0.f;
#pragma unroll
        for (int kf = 0; kf < 8; kf++){
            int kc = kf*8 + (lane & 3);
            int rbase = w*16 + (lane >> 2);
            unsigned a0 = Qs[(rbase    )*68 + kc    ];
            unsigned a1 = Qs[(rbase + 8)*68 + kc    ];
            unsigned a2 = Qs[(rbase    )*68 + kc + 4];
            unsigned a3 = Qs[(rbase + 8)*68 + kc + 4];
#pragma unroll
            for (int nf = 0; nf < 8; nf++){
                int nb = nf*8 + (lane >> 2);
                unsigned b0 = Ks[nb*68 + kc];
                unsigned b1 = Ks[nb*68 + kc + 4];
                mma_tf32(S[nf][0], S[nf][1], S[nf][2], S[nf][3], a0, a1, a2, a3, b0, b1);
            }
        }

        // bias + scale, validity
        bool kval[8][2];
#pragma unroll
        for (int nf = 0; nf < 8; nf++){
#pragma unroll
            for (int j = 0; j < 2; j++){
                int kl = nf*8 + (lane & 3)*2 + j;
                int kn = k0 + kl;
                kval[nf][j] = (kn < CN);
                float ky, kx;
                tok_coord(kn, ky, kx);
                float kd = kdep[kl];
#pragma unroll
                for (int i = 0; i < 2; i++){
                    float pos = fabsf(qy[i]-ky) + fabsf(qx[i]-kx);
                    float vv = S[nf][i*2+j]*0.125f + w0*pos + w1*fabsf(qd[i]-kd);
                    S[nf][i*2+j] = kval[nf][j] ? vv : -1e30f;
                }
            }
        }

        // online softmax per row (quad reduction)
        float alpha[2];
#pragma unroll
        for (int i = 0; i < 2; i++){
            float tm = -1e30f;
#pragma unroll
            for (int nf = 0; nf < 8; nf++){
                tm = fmaxf(tm, S[nf][i*2]);
                tm = fmaxf(tm, S[nf][i*2+1]);
            }
            tm = fmaxf(tm, __shfl_xor_sync(0xffffffffu, tm, 1));
            tm = fmaxf(tm, __shfl_xor_sync(0xffffffffu, tm, 2));
            float mn = fmaxf(mi[i], tm);
            alpha[i] = __expf(mi[i] - mn);
            float ssum = 0.f;
#pragma unroll
            for (int nf = 0; nf < 8; nf++){
#pragma unroll
                for (int j = 0; j < 2; j++){
                    float p = kval[nf][j] ? __expf(S[nf][i*2+j] - mn) : 0.f;
                    S[nf][i*2+j] = p;
                    ssum += p;
                }
            }
            ssum += __shfl_xor_sync(0xffffffffu, ssum, 1);
            ssum += __shfl_xor_sync(0xffffffffu, ssum, 2);
            li[i] = li[i]*alpha[i] + ssum;
            mi[i] = mn;
        }
        // rescale O
#pragma unroll
        for (int nf = 0; nf < 8; nf++){
            O[nf][0] *= alpha[0]; O[nf][1] *= alpha[0];
            O[nf][2] *= alpha[1]; O[nf][3] *= alpha[1];
        }
        // write P to smem (warp-private rows)
#pragma unroll
        for (int nf = 0; nf < 8; nf++){
#pragma unroll
            for (int i = 0; i < 2; i++){
                int r = w*16 + (lane >> 2) + i*8;
                int c = nf*8 + (lane & 3)*2;
                Ps[r*68 + c]     = f2tf(S[nf][i*2]);
                Ps[r*68 + c + 1] = f2tf(S[nf][i*2+1]);
            }
        }
        __syncwarp();

        // O += P V
#pragma unroll
        for (int kf = 0; kf < 8; kf++){
            int kc = kf*8 + (lane & 3);
            int rbase = w*16 + (lane >> 2);
            unsigned a0 = Ps[(rbase    )*68 + kc    ];
            unsigned a1 = Ps[(rbase + 8)*68 + kc    ];
            unsigned a2 = Ps[(rbase    )*68 + kc + 4];
            unsigned a3 = Ps[(rbase + 8)*68 + kc + 4];
#pragma unroll
            for (int nf = 0; nf < 8; nf++){
                unsigned b0 = Vs[(kf*8 + (lane & 3)    )*72 + nf*8 + (lane >> 2)];
                unsigned b1 = Vs[(kf*8 + (lane & 3) + 4)*72 + nf*8 + (lane >> 2)];
                mma_tf32(O[nf][0], O[nf][1], O[nf][2], O[nf][3], a0, a1, a2, a3, b0, b1);
            }
        }
    }

    // epilogue
#pragma unroll
    for (int i = 0; i < 2; i++){
        int qn = q0 + w*16 + (lane >> 2) + i*8;
        if (qn >= CN) continue;
        float invl = 1.f / li[i];
        size_t base = ((size_t)b*CN + qn)*CC + h*64;
#pragma unroll
        for (int nf = 0; nf < 8; nf++){
            int c = nf*8 + (lane & 3)*2;
            *(float2*)(ao + base + c) = make_float2(O[nf][i*2]*invl, O[nf][i*2+1]*invl);
        }
    }
}

// ---------------- final: out = fused + BN(op_pw output), with transpose ----------------
__global__ void k_final(const float* __restrict__ fused, const float* __restrict__ o2t,
                        const float* __restrict__ bn, float* __restrict__ out)
{
    __shared__ float tile[32][33];
    int b = blockIdx.z;
    int p0 = blockIdx.x * 32, c0 = blockIdx.y * 32;
    int tx = threadIdx.x, ty = threadIdx.y;
#pragma unroll
    for (int i = 0; i < 4; i++){
        int p = p0 + ty + i*8;
        tile[ty + i*8][tx] = o2t[((size_t)b*CHW + p)*CC + c0 + tx];
    }
    __syncthreads();
#pragma unroll
    for (int i = 0; i < 4; i++){
        int c = c0 + ty + i*8;
        float s = bn[c] * rsqrtf(bn[3*CC+c] + EPS);
        float t = bn[CC+c] - bn[2*CC+c] * s;
        size_t idx = ((size_t)b*CC + c)*CHW + p0 + tx;
        out[idx] = fused[idx] + tile[tx][ty + i*8] * s + t;
    }
}

// ---------------- host ----------------
static void launch_gemm(int epi, const float* A, const float* Bw, float* Cm,
                        int M, int N, int K, const float* ep, const float* res)
{
    dim3 g(N/128, (M + 127)/128);
    switch (epi){
        case 0: k_gemm_tc<0><<<g,256>>>(A,Bw,Cm,M,N,K,ep,res); break;
        case 1: k_gemm_tc<1><<<g,256>>>(A,Bw,Cm,M,N,K,ep,res); break;
        case 2: k_gemm_tc<2><<<g,256>>>(A,Bw,Cm,M,N,K,ep,res); break;
        case 3: k_gemm_tc<3><<<g,256>>>(A,Bw,Cm,M,N,K,ep,res); break;
        case 4: k_gemm_tc<4><<<g,256>>>(A,Bw,Cm,M,N,K,ep,res); break;
    }
}

extern "C" void kernel_launch(void* const* d_in, const int* in_sizes, int n_in,
                              void* d_out, int out_size)
{
    const float* fused        = (const float*)d_in[0];
    const float* depth        = (const float*)d_in[1];
    const float* pg_dw_w      = (const float*)d_in[2];
    const float* pg_bn1       = (const float*)d_in[3];
    const float* pg_pw_w      = (const float*)d_in[4];
    const float* pg_bn2       = (const float*)d_in[5];
    const float* prompt_embed = (const float*)d_in[6];
    const float* pg_ln        = (const float*)d_in[7];
    const float* gp_dw_w      = (const float*)d_in[8];
    const float* gp_bn        = (const float*)d_in[9];
    const float* gp_pw_w      = (const float*)d_in[10];
    const float* gp_pw_b      = (const float*)d_in[11];
    const float* gp_weight    = (const float*)d_in[12];
    const float* ln1          = (const float*)d_in[13];
    const float* wq           = (const float*)d_in[14];
    const float* wk           = (const float*)d_in[15];
    const float* wv           = (const float*)d_in[16];
    const float* wo           = (const float*)d_in[17];
    const float* ln2          = (const float*)d_in[18];
    const float* mlp_w1       = (const float*)d_in[19];
    const float* mlp_b1       = (const float*)d_in[20];
    const float* mlp_w2       = (const float*)d_in[21];
    const float* mlp_b2       = (const float*)d_in[22];
    const float* op_dw_w      = (const float*)d_in[23];
    const float* op_bn1       = (const float*)d_in[24];
    const float* op_pw_w      = (const float*)d_in[25];
    const float* op_bn2       = (const float*)d_in[26];

    float *dw1,*dsf,*pp1t,*pp2t,*ds,*prm,*jdb,*jt,*xb,*qb,*kb,*vb,*aob,*hb,*enh,*o1c,*o1t,*o2t;
    cudaGetSymbolAddress((void**)&dw1,  g_dw1);
    cudaGetSymbolAddress((void**)&dsf,  g_dsf);
    cudaGetSymbolAddress((void**)&pp1t, g_pp1t);
    cudaGetSymbolAddress((void**)&pp2t, g_pp2t);
    cudaGetSymbolAddress((void**)&ds,   g_ds);
    cudaGetSymbolAddress((void**)&prm,  g_prompt);
    cudaGetSymbolAddress((void**)&jdb,  g_jd);
    cudaGetSymbolAddress((void**)&jt,   g_jt);
    cudaGetSymbolAddress((void**)&xb,   g_x);
    cudaGetSymbolAddress((void**)&qb,   g_q);
    cudaGetSymbolAddress((void**)&kb,   g_k);
    cudaGetSymbolAddress((void**)&vb,   g_v);
    cudaGetSymbolAddress((void**)&aob,  g_ao);
    cudaGetSymbolAddress((void**)&hb,   g_h);
    cudaGetSymbolAddress((void**)&enh,  g_enh);
    cudaGetSymbolAddress((void**)&o1c,  g_o1c);
    cudaGetSymbolAddress((void**)&o1t,  g_o1t);
    cudaGetSymbolAddress((void**)&o2t,  g_o2t);

    cudaFuncSetAttribute(k_attn, cudaFuncAttributeMaxDynamicSharedMemorySize, ATTN_SMEM);

    dim3 tgrid(CHW/32, CC/32, CB), tblk(32, 8);

    // --- DepthPromptGenerator + GeometryPriorGenerator shared dwconv ---
    k_dwconv_dual<<<(CB*CC*CHW)/256, 256>>>(depth, pg_dw_w, pg_bn1, dw1, gp_dw_w, gp_bn, dsf);
    k_cp_to_tok<<<tgrid, tblk>>>(dw1, pp1t, CHW, 0);
    launch_gemm(1, pp1t, pg_pw_w, pp2t, CB*CHW, CC, CC, pg_bn2, nullptr);   // bn2 + gelu
    k_gp_pw<<<(CB*CHW)/32, 256>>>(dsf, gp_pw_w, gp_pw_b, ds);
    k_prompt<<<CB*NPR, 256>>>(pp2t, prompt_embed, pg_ln, prm);
    k_jd<<<(CB*CN + 255)/256, 256>>>(ds, jdb);

    // --- assemble joint tokens ---
    k_copy_prompt<<<(CB*NPR*CC)/256, 256>>>(prm, jt);
    k_cp_to_tok<<<tgrid, tblk>>>(fused, jt, CN, NPR);

    // --- attention block ---
    k_ln<<<CB*CN, 256>>>(jt, ln1, xb);
    launch_gemm(0, xb, wq, qb, CB*CN, CC, CC, nullptr, nullptr);
    launch_gemm(0, xb, wk, kb, CB*CN, CC, CC, nullptr, nullptr);
    launch_gemm(0, xb, wv, vb, CB*CN, CC, CC, nullptr, nullptr);
    k_attn<<<dim3(9, CNH, CB), 256, ATTN_SMEM>>>(qb, kb, vb, jdb, gp_weight, aob);
    launch_gemm(4, aob, wo, jt, CB*CN, CC, CC, nullptr, jt);                // jt += ao@wo^T

    // --- MLP ---
    k_ln<<<CB*CN, 256>>>(jt, ln2, xb);
    launch_gemm(2, xb, mlp_w1, hb, CB*CN, HID, CC, mlp_b1, nullptr);        // bias + gelu
    launch_gemm(3, hb, mlp_w2, jt, CB*CN, CC, HID, mlp_b2, jt);             // bias + residual

    // --- out_proj ---
    k_tok_to_cp<<<tgrid, tblk>>>(jt, enh, CN, NPR);
    k_dwconv_dual<<<(CB*CC*CHW)/256, 256>>>(enh, op_dw_w, op_bn1, o1c, nullptr, nullptr, nullptr);
    k_cp_to_tok<<<tgrid, tblk>>>(o1c, o1t, CHW, 0);
    launch_gemm(0, o1t, op_pw_w, o2t, CB*CHW, CC, CC, nullptr, nullptr);
    k_final<<<tgrid, tblk>>>(fused, o2t, op_bn2, (float*)d_out);
}

// round 4
// speedup vs baseline: 4.3794x; 1.0019x over previous
#include <cuda_runtime.h>
#include <math.h>

// ---------------- problem constants ----------------
constexpr int CB  = 4;      // batch
constexpr int CC  = 512;    // channels
constexpr int CHH = 32;     // H
constexpr int CWW = 32;     // W
constexpr int CHW = 1024;   // H*W
constexpr int CNH = 8;      // heads
constexpr int NPR = 8;      // prompt tokens
constexpr int CN  = 1032;   // total tokens
constexpr int HID = 1024;   // mlp hidden
constexpr float EPS = 1e-5f;

// ---------------- scratch (static device memory; no allocations) ----------------
__device__ __align__(16) float g_dw1 [CB*CC*CHW];
__device__ __align__(16) float g_dsf [CB*CC*CHW];
__device__ __align__(16) float g_pp1t[CB*CHW*CC];
__device__ __align__(16) float g_pp2t[CB*CHW*CC];
__device__ __align__(16) float g_ds  [CB*CHW];
__device__ __align__(16) float g_prompt[CB*NPR*CC];
__device__ __align__(16) float g_jd  [CB*CN];
__device__ __align__(16) float g_jt  [CB*CN*CC];
__device__ __align__(16) float g_x   [CB*CN*CC];
__device__ __align__(16) float g_q   [CB*CN*CC];
__device__ __align__(16) float g_k   [CB*CN*CC];
__device__ __align__(16) float g_v   [CB*CN*CC];
__device__ __align__(16) float g_ao  [CB*CN*CC];
__device__ __align__(16) float g_h   [CB*CN*HID];
__device__ __align__(16) float g_enh [CB*CC*CHW];
__device__ __align__(16) float g_o1c [CB*CC*CHW];
__device__ __align__(16) float g_o1t [CB*CHW*CC];
__device__ __align__(16) float g_o2t [CB*CHW*CC];

__device__ __forceinline__ float gelu_f(float x){
    return 0.5f * x * (1.0f + erff(x * 0.70710678118654752f));
}

__device__ __forceinline__ unsigned f2tf(float f){
    unsigned u;
    asm("cvt.rna.tf32.f32 %0, %1;" : "=r"(u) : "f"(f));
    return u;
}

__device__ __forceinline__ void mma_tf32(float& d0, float& d1, float& d2, float& d3,
                                         unsigned a0, unsigned a1, unsigned a2, unsigned a3,
                                         unsigned b0, unsigned b1)
{
    asm volatile("mma.sync.aligned.m16n8k8.row.col.f32.tf32.tf32.f32 "
                 "{%0,%1,%2,%3}, {%4,%5,%6,%7}, {%8,%9}, {%0,%1,%2,%3};"
                 : "+f"(d0), "+f"(d1), "+f"(d2), "+f"(d3)
                 : "r"(a0), "r"(a1), "r"(a2), "r"(a3), "r"(b0), "r"(b1));
}

// ---------------- depthwise 3x3 conv + BN + GELU (optionally two branches) ----------------
__global__ void k_dwconv_dual(const float* __restrict__ in,
                              const float* __restrict__ w1, const float* __restrict__ bn1,
                              float* __restrict__ out1,
                              const float* __restrict__ w2, const float* __restrict__ bn2,
                              float* __restrict__ out2)
{
    int idx = blockIdx.x * 256 + threadIdx.x;
    if (idx >= CB*CC*CHW) return;
    int p = idx & (CHW-1);
    int c = (idx >> 10) & (CC-1);
    int y = p >> 5, x = p & 31;
    const float* base = in + (size_t)(idx - p);
    float v[9];
#pragma unroll
    for (int ky = 0; ky < 3; ky++)
#pragma unroll
        for (int kx = 0; kx < 3; kx++){
            int yy = y + ky - 1, xx = x + kx - 1;
            v[ky*3+kx] = (yy >= 0 && yy < CHH && xx >= 0 && xx < CWW) ? base[yy*CWW + xx] : 0.f;
        }
    {
        float a = 0.f;
#pragma unroll
        for (int k = 0; k < 9; k++) a += w1[c*9+k] * v[k];
        float s = bn1[c] * rsqrtf(bn1[3*CC+c] + EPS);
        a = a * s + bn1[CC+c] - bn1[2*CC+c] * s;
        out1[idx] = gelu_f(a);
    }
    if (out2){
        float a = 0.f;
#pragma unroll
        for (int k = 0; k < 9; k++) a += w2[c*9+k] * v[k];
        float s = bn2[c] * rsqrtf(bn2[3*CC+c] + EPS);
        a = a * s + bn2[CC+c] - bn2[2*CC+c] * s;
        out2[idx] = gelu_f(a);
    }
}

// ---------------- transposes ----------------
__global__ void k_cp_to_tok(const float* __restrict__ in, float* __restrict__ out,
                            int tokTotal, int tokOff)
{
    __shared__ float tile[32][33];
    int b = blockIdx.z;
    int p0 = blockIdx.x * 32, c0 = blockIdx.y * 32;
    int tx = threadIdx.x, ty = threadIdx.y;
#pragma unroll
    for (int i = 0; i < 4; i++){
        int c = c0 + ty + i*8;
        tile[ty + i*8][tx] = in[((size_t)b*CC + c)*CHW + p0 + tx];
    }
    __syncthreads();
#pragma unroll
    for (int i = 0; i < 4; i++){
        int p = p0 + ty + i*8;
        out[((size_t)b*tokTotal + tokOff + p)*CC + c0 + tx] = tile[tx][ty + i*8];
    }
}

__global__ void k_tok_to_cp(const float* __restrict__ in, float* __restrict__ out,
                            int tokTotal, int tokOff)
{
    __shared__ float tile[32][33];
    int b = blockIdx.z;
    int p0 = blockIdx.x * 32, c0 = blockIdx.y * 32;
    int tx = threadIdx.x, ty = threadIdx.y;
#pragma unroll
    for (int i = 0; i < 4; i++){
        int p = p0 + ty + i*8;
        tile[ty + i*8][tx] = in[((size_t)b*tokTotal + tokOff + p)*CC + c0 + tx];
    }
    __syncthreads();
#pragma unroll
    for (int i = 0; i < 4; i++){
        int c = c0 + ty + i*8;
        out[((size_t)b*CC + c)*CHW + p0 + tx] = tile[tx][ty + i*8];
    }
}

// ---------------- tensor-core NT GEMM (tf32 mma), 128x128 tile, K-step 16 ----------------
// C[m,n] = sum_k A[m,k]*B[n,k].  EPI: 0 plain, 1 bn+gelu, 2 bias+gelu, 3 bias+res, 4 res
constexpr int GST = 20;   // padded SMEM stride (words), conflict-free for mma frag loads

template<int EPI>
__global__ void __launch_bounds__(256) k_gemm_tc(const float* __restrict__ A,
                                                 const float* __restrict__ Bw,
                                                 float* __restrict__ Cmat,
                                                 int M, int N, int K,
                                                 const float* __restrict__ ep,
                                                 const float* __restrict__ res)
{
    __shared__ unsigned As[2][128*GST];
    __shared__ unsigned Bs[2][128*GST];

    int tid  = threadIdx.x;
    int lane = tid & 31;
    int w    = tid >> 5;
    int wm   = w >> 1;         // 0..3 (M)
    int wn   = w & 1;          // 0..1 (N)
    int m0 = blockIdx.y * 128, n0 = blockIdx.x * 128;

    // load indices: 512 float4 per tile, 2 per thread
    int i0 = tid, i1 = tid + 256;
    int ar0 = i0 >> 2, ac0 = (i0 & 3) * 4;
    int ar1 = i1 >> 2, ac1 = (i1 & 3) * 4;

    float acc[2][8][4];
#pragma unroll
    for (int mf = 0; mf < 2; mf++)
#pragma unroll
        for (int nf = 0; nf < 8; nf++)
#pragma unroll
            for (int r = 0; r < 4; r++) acc[mf][nf][r] = 0.f;

    int NK = K >> 4;

    // prologue: tile 0
    {
        float4 a0 = (m0 + ar0 < M) ? *(const float4*)(A + (size_t)(m0 + ar0)*K + ac0) : make_float4(0,0,0,0);
        float4 a1 = (m0 + ar1 < M) ? *(const float4*)(A + (size_t)(m0 + ar1)*K + ac1) : make_float4(0,0,0,0);
        float4 b0 = *(const float4*)(Bw + (size_t)(n0 + ar0)*K + ac0);
        float4 b1 = *(const float4*)(Bw + (size_t)(n0 + ar1)*K + ac1);
        *(uint4*)&As[0][ar0*GST + ac0] = make_uint4(f2tf(a0.x), f2tf(a0.y), f2tf(a0.z), f2tf(a0.w));
        *(uint4*)&As[0][ar1*GST + ac1] = make_uint4(f2tf(a1.x), f2tf(a1.y), f2tf(a1.z), f2tf(a1.w));
        *(uint4*)&Bs[0][ar0*GST + ac0] = make_uint4(f2tf(b0.x), f2tf(b0.y), f2tf(b0.z), f2tf(b0.w));
        *(uint4*)&Bs[0][ar1*GST + ac1] = make_uint4(f2tf(b1.x), f2tf(b1.y), f2tf(b1.z), f2tf(b1.w));
    }
    __syncthreads();

    for (int kt = 0; kt < NK; kt++){
        float4 a0, a1, b0, b1;
        bool has_next = (kt + 1 < NK);
        if (has_next){
            int kb = (kt + 1) << 4;
            a0 = (m0 + ar0 < M) ? *(const float4*)(A + (size_t)(m0 + ar0)*K + kb + ac0) : make_float4(0,0,0,0);
            a1 = (m0 + ar1 < M) ? *(const float4*)(A + (size_t)(m0 + ar1)*K + kb + ac1) : make_float4(0,0,0,0);
            b0 = *(const float4*)(Bw + (size_t)(n0 + ar0)*K + kb + ac0);
            b1 = *(const float4*)(Bw + (size_t)(n0 + ar1)*K + kb + ac1);
        }
        const unsigned* Ac = As[kt & 1];
        const unsigned* Bc = Bs[kt & 1];
#pragma unroll
        for (int kf = 0; kf < 2; kf++){
            int kc = kf*8 + (lane & 3);
            unsigned afr[2][4];
#pragma unroll
            for (int mf = 0; mf < 2; mf++){
                int rbase = wm*32 + mf*16 + (lane >> 2);
                afr[mf][0] = Ac[(rbase    )*GST + kc    ];
                afr[mf][1] = Ac[(rbase + 8)*GST + kc    ];
                afr[mf][2] = Ac[(rbase    )*GST + kc + 4];
                afr[mf][3] = Ac[(rbase + 8)*GST + kc + 4];
            }
#pragma unroll
            for (int nf = 0; nf < 8; nf++){
                int nb = wn*64 + nf*8 + (lane >> 2);
                unsigned bb0 = Bc[nb*GST + kc];
                unsigned bb1 = Bc[nb*GST + kc + 4];
#pragma unroll
                for (int mf = 0; mf < 2; mf++)
                    mma_tf32(acc[mf][nf][0], acc[mf][nf][1], acc[mf][nf][2], acc[mf][nf][3],
                             afr[mf][0], afr[mf][1], afr[mf][2], afr[mf][3], bb0, bb1);
            }
        }
        if (has_next){
            unsigned bi = (kt + 1) & 1;
            *(uint4*)&As[bi][ar0*GST + ac0] = make_uint4(f2tf(a0.x), f2tf(a0.y), f2tf(a0.z), f2tf(a0.w));
            *(uint4*)&As[bi][ar1*GST + ac1] = make_uint4(f2tf(a1.x), f2tf(a1.y), f2tf(a1.z), f2tf(a1.w));
            *(uint4*)&Bs[bi][ar0*GST + ac0] = make_uint4(f2tf(b0.x), f2tf(b0.y), f2tf(b0.z), f2tf(b0.w));
            *(uint4*)&Bs[bi][ar1*GST + ac1] = make_uint4(f2tf(b1.x), f2tf(b1.y), f2tf(b1.z), f2tf(b1.w));
        }
        __syncthreads();
    }

    // epilogue
#pragma unroll
    for (int mf = 0; mf < 2; mf++){
#pragma unroll
        for (int ri = 0; ri < 2; ri++){
            int row = m0 + wm*32 + mf*16 + (lane >> 2) + ri*8;
            if (row >= M) continue;
            size_t base = (size_t)row * N;
#pragma unroll
            for (int nf = 0; nf < 8; nf++){
                int col = n0 + wn*64 + nf*8 + 2*(lane & 3);
                float v0 = acc[mf][nf][ri*2 + 0];
                float v1 = acc[mf][nf][ri*2 + 1];
                if (EPI == 1){
                    float s0 = ep[col]   * rsqrtf(ep[3*N+col]   + EPS);
                    float s1 = ep[col+1] * rsqrtf(ep[3*N+col+1] + EPS);
                    v0 = gelu_f(v0 * s0 + ep[N+col]   - ep[2*N+col]   * s0);
                    v1 = gelu_f(v1 * s1 + ep[N+col+1] - ep[2*N+col+1] * s1);
                } else if (EPI == 2){
                    v0 = gelu_f(v0 + ep[col]);
                    v1 = gelu_f(v1 + ep[col+1]);
                } else if (EPI == 3){
                    float2 rr = *(const float2*)(res + base + col);
                    v0 = rr.x + v0 + ep[col];
                    v1 = rr.y + v1 + ep[col+1];
                } else if (EPI == 4){
                    float2 rr = *(const float2*)(res + base + col);
                    v0 = rr.x + v0;
                    v1 = rr.y + v1;
                }
                *(float2*)(Cmat + base + col) = make_float2(v0, v1);
            }
        }
    }
}

// ---------------- geometry prior: 512->1 projection (parallel) ----------------
__global__ void k_gp_pw(const float* __restrict__ dsf, const float* __restrict__ w,
                        const float* __restrict__ bias, float* __restrict__ ds)
{
    // block: 256 threads = 32 pixels x 8 channel-chunks of 64
    __shared__ float red[8][33];
    int px = threadIdx.x & 31;
    int cz = threadIdx.x >> 5;
    int p0 = blockIdx.x * 32;
    int b  = p0 >> 10;
    int p  = (p0 & (CHW-1)) + px;
    float acc = 0.f;
#pragma unroll
    for (int i = 0; i < 64; i++){
        int c = cz*64 + i;
        acc += w[c] * dsf[((size_t)b*CC + c)*CHW + p];
    }
    red[cz][px] = acc;
    __syncthreads();
    if (cz == 0){
        float s = 0.f;
#pragma unroll
        for (int z = 0; z < 8; z++) s += red[z][px];
        ds[p0 + px] = s + bias[0];
    }
}

// ---------------- prompt: pool + embed + LN ----------------
__global__ void k_prompt(const float* __restrict__ pp2t, const float* __restrict__ pe,
                         const float* __restrict__ lnp, float* __restrict__ out)
{
    int b = blockIdx.x >> 3, pr = blockIdx.x & 7;
    int iy = pr >> 2, ix = pr & 3;
    int t = threadIdx.x;
    float a0 = 0.f, a1 = 0.f;
    for (int py = 0; py < 16; py++)
        for (int px = 0; px < 8; px++){
            int p = (iy*16 + py)*CWW + ix*8 + px;
            const float* base = pp2t + ((size_t)b*CHW + p)*CC;
            a0 += base[t];
            a1 += base[t + 256];
        }
    a0 = a0 * (1.f/128.f) + pe[pr*CC + t];
    a1 = a1 * (1.f/128.f) + pe[pr*CC + t + 256];
    __shared__ float rs[256], rq[256];
    rs[t] = a0 + a1; rq[t] = a0*a0 + a1*a1;
    __syncthreads();
    for (int s = 128; s > 0; s >>= 1){
        if (t < s){ rs[t] += rs[t+s]; rq[t] += rq[t+s]; }
        __syncthreads();
    }
    float mean = rs[0] * (1.f/512.f);
    float var  = rq[0] * (1.f/512.f) - mean*mean;
    float inv  = rsqrtf(var + EPS);
    size_t o = ((size_t)b*NPR + pr) * CC;
    out[o + t]       = (a0 - mean) * inv * lnp[t]       + lnp[CC + t];
    out[o + t + 256] = (a1 - mean) * inv * lnp[t + 256] + lnp[CC + t + 256];
}

// ---------------- joint depth scalar per token ----------------
__global__ void k_jd(const float* __restrict__ ds, float* __restrict__ jd)
{
    int t = blockIdx.x * 256 + threadIdx.x;
    if (t >= CB*CN) return;
    int b = t / CN, n = t % CN;
    if (n >= NPR){
        jd[t] = ds[b*CHW + (n - NPR)];
    } else {
        int iy = n >> 2, ix = n & 3;
        float acc = 0.f;
        for (int py = 0; py < 16; py++)
            for (int px = 0; px < 8; px++)
                acc += ds[b*CHW + (iy*16 + py)*CWW + ix*8 + px];
        jd[t] = acc * (1.f/128.f);
    }
}

// ---------------- copy prompt tokens into jt ----------------
__global__ void k_copy_prompt(const float* __restrict__ pr, float* __restrict__ jt)
{
    int idx = blockIdx.x * 256 + threadIdx.x;
    if (idx >= CB*NPR*CC) return;
    int b = idx / (NPR*CC), r = idx % (NPR*CC);
    jt[(size_t)b*CN*CC + r] = pr[(size_t)b*NPR*CC + r];
}

// ---------------- layernorm over C per token ----------------
__global__ void k_ln(const float* __restrict__ in, const float* __restrict__ p,
                     float* __restrict__ out)
{
    int tok = blockIdx.x;
    const float* row = in + (size_t)tok * CC;
    int t = threadIdx.x;
    float v0 = row[t], v1 = row[t + 256];
    __shared__ float rs[256], rq[256];
    rs[t] = v0 + v1; rq[t] = v0*v0 + v1*v1;
    __syncthreads();
    for (int s = 128; s > 0; s >>= 1){
        if (t < s){ rs[t] += rs[t+s]; rq[t] += rq[t+s]; }
        __syncthreads();
    }
    float mean = rs[0] * (1.f/512.f);
    float var  = rq[0] * (1.f/512.f) - mean*mean;
    float inv  = rsqrtf(var + EPS);
    size_t o = (size_t)tok * CC;
    out[o + t]       = (v0 - mean) * inv * p[t]       + p[CC + t];
    out[o + t + 256] = (v1 - mean) * inv * p[t + 256] + p[CC + t + 256];
}

// ---------------- attention: flash-style, tf32 mma, analytic bias ----------------
__device__ __forceinline__ void tok_coord(int n, float& cy, float& cx){
    if (n < NPR){ cy = (float)(n >> 2); cx = (float)(n & 3) * (1.f/3.f); }
    else { int m = n - NPR; cy = (float)(m >> 5) * (1.f/31.f); cx = (float)(m & 31) * (1.f/31.f); }
}

constexpr int QS_OFF = 0;                    // 128 x 68
constexpr int KS_OFF = QS_OFF + 128*68;      // 64 x 68
constexpr int VS_OFF = KS_OFF + 64*68;       // 64 x 72
constexpr int PS_OFF = VS_OFF + 64*72;       // 128 x 68
constexpr int KD_OFF = PS_OFF + 128*68;      // 64 floats
constexpr int ATTN_SMEM = (KD_OFF + 64) * 4; // bytes

__global__ void __launch_bounds__(256) k_attn(const float* __restrict__ qg,
                                              const float* __restrict__ kg,
                                              const float* __restrict__ vg,
                                              const float* __restrict__ jd,
                                              const float* __restrict__ gw,
                                              float* __restrict__ ao)
{
    extern __shared__ unsigned smu[];
    unsigned* Qs = smu + QS_OFF;
    unsigned* Ks = smu + KS_OFF;
    unsigned* Vs = smu + VS_OFF;
    unsigned* Ps = smu + PS_OFF;
    float*  kdep = (float*)(smu + KD_OFF);

    int b = blockIdx.z, h = blockIdx.y, q0 = blockIdx.x * 128;
    int tid = threadIdx.x, lane = tid & 31, w = tid >> 5;

    const float decay = logf(1.f - exp2f(-1.f - 0.5f * (float)h));
    const float w0 = gw[0] * decay, w1 = gw[1] * decay;

    // load Q tile (128 x 64), tf32, stride 68
    {
#pragma unroll
        for (int j = 0; j < 8; j++){
            int i = tid + 256*j;            // float4 index: 16 per row
            int r = i >> 4, c4 = (i & 15) * 4;
            int qn = q0 + r;
            float4 v = (qn < CN) ? *(const float4*)(qg + ((size_t)b*CN + qn)*CC + h*64 + c4)
                                 : make_float4(0,0,0,0);
            *(uint4*)&Qs[r*68 + c4] = make_uint4(f2tf(v.x), f2tf(v.y), f2tf(v.z), f2tf(v.w));
        }
    }

    // q-row metadata (2 rows per thread)
    float qy[2], qx[2], qd[2];
#pragma unroll
    for (int i = 0; i < 2; i++){
        int qn = q0 + w*16 + (lane >> 2) + i*8;
        if (qn < CN){ tok_coord(qn, qy[i], qx[i]); qd[i] = jd[b*CN + qn]; }
        else { qy[i] = qx[i] = qd[i] = 0.f; }
    }

    float O[8][4];
#pragma unroll
    for (int nf = 0; nf < 8; nf++)
#pragma unroll
        for (int r = 0; r < 4; r++) O[nf][r] = 0.f;
    float mi[2] = {-1e30f, -1e30f}, li[2] = {0.f, 0.f};

    for (int kt = 0; kt < 17; kt++){
        int k0 = kt * 64;
        __syncthreads();   // previous tile fully consumed
        // load K, V tiles (64 x 64)
#pragma unroll
        for (int j = 0; j < 4; j++){
            int i = tid + 256*j;
            int r = i >> 4, c4 = (i & 15) * 4;
            int n = k0 + r;
            bool val = (n < CN);
            float4 kv = val ? *(const float4*)(kg + ((size_t)b*CN + n)*CC + h*64 + c4) : make_float4(0,0,0,0);
            float4 vv = val ? *(const float4*)(vg + ((size_t)b*CN + n)*CC + h*64 + c4) : make_float4(0,0,0,0);
            *(uint4*)&Ks[r*68 + c4] = make_uint4(f2tf(kv.x), f2tf(kv.y), f2tf(kv.z), f2tf(kv.w));
            *(uint4*)&Vs[r*72 + c4] = make_uint4(f2tf(vv.x), f2tf(vv.y), f2tf(vv.z), f2tf(vv.w));
        }
        if (tid < 64) kdep[tid] = (k0 + tid < CN) ? jd[b*CN + k0 + tid] : 0.f;
        __syncthreads();

        // S = Q K^T (warp computes its 16 rows x 64 cols)
        float S[8][4];
#pragma unroll
        for (int nf = 0; nf < 8; nf++)
#pragma unroll
            for (int r = 0; r < 4; r++) S[nf][r] = 0.f;
#pragma unroll
        for (int kf = 0; kf < 8; kf++){
            int kc = kf*8 + (lane & 3);
            int rbase = w*16 + (lane >> 2);
            unsigned a0 = Qs[(rbase    )*68 + kc    ];
            unsigned a1 = Qs[(rbase + 8)*68 + kc    ];
            unsigned a2 = Qs[(rbase    )*68 + kc + 4];
            unsigned a3 = Qs[(rbase + 8)*68 + kc + 4];
#pragma unroll
            for (int nf = 0; nf < 8; nf++){
                int nb = nf*8 + (lane >> 2);
                unsigned b0 = Ks[nb*68 + kc];
                unsigned b1 = Ks[nb*68 + kc + 4];
                mma_tf32(S[nf][0], S[nf][1], S[nf][2], S[nf][3], a0, a1, a2, a3, b0, b1);
            }
        }

        // bias + scale, validity
        bool kval[8][2];
#pragma unroll
        for (int nf = 0; nf < 8; nf++){
#pragma unroll
            for (int j = 0; j < 2; j++){
                int kl = nf*8 + (lane & 3)*2 + j;
                int kn = k0 + kl;
                kval[nf][j] = (kn < CN);
                float ky, kx;
                tok_coord(kn, ky, kx);
                float kd = kdep[kl];
#pragma unroll
                for (int i = 0; i < 2; i++){
                    float pos = fabsf(qy[i]-ky) + fabsf(qx[i]-kx);
                    float vv = S[nf][i*2+j]*0.125f + w0*pos + w1*fabsf(qd[i]-kd);
                    S[nf][i*2+j] = kval[nf][j] ? vv : -1e30f;
                }
            }
        }

        // online softmax per row (quad reduction)
        float alpha[2];
#pragma unroll
        for (int i = 0; i < 2; i++){
            float tm = -1e30f;
#pragma unroll
            for (int nf = 0; nf < 8; nf++){
                tm = fmaxf(tm, S[nf][i*2]);
                tm = fmaxf(tm, S[nf][i*2+1]);
            }
            tm = fmaxf(tm, __shfl_xor_sync(0xffffffffu, tm, 1));
            tm = fmaxf(tm, __shfl_xor_sync(0xffffffffu, tm, 2));
            float mn = fmaxf(mi[i], tm);
            alpha[i] = __expf(mi[i] - mn);
            float ssum = 0.f;
#pragma unroll
            for (int nf = 0; nf < 8; nf++){
#pragma unroll
                for (int j = 0; j < 2; j++){
                    float p = kval[nf][j] ? __expf(S[nf][i*2+j] - mn) : 0.f;
                    S[nf][i*2+j] = p;
                    ssum += p;
                }
            }
            ssum += __shfl_xor_sync(0xffffffffu, ssum, 1);
            ssum += __shfl_xor_sync(0xffffffffu, ssum, 2);
            li[i] = li[i]*alpha[i] + ssum;
            mi[i] = mn;
        }
        // rescale O
#pragma unroll
        for (int nf = 0; nf < 8; nf++){
            O[nf][0] *= alpha[0]; O[nf][1] *= alpha[0];
            O[nf][2] *= alpha[1]; O[nf][3] *= alpha[1];
        }
        // write P to smem (warp-private rows)
#pragma unroll
        for (int nf = 0; nf < 8; nf++){
#pragma unroll
            for (int i = 0; i < 2; i++){
                int r = w*16 + (lane >> 2) + i*8;
                int c = nf*8 + (lane & 3)*2;
                Ps[r*68 + c]     = f2tf(S[nf][i*2]);
                Ps[r*68 + c + 1] = f2tf(S[nf][i*2+1]);
            }
        }
        __syncwarp();

        // O += P V
#pragma unroll
        for (int kf = 0; kf < 8; kf++){
            int kc = kf*8 + (lane & 3);
            int rbase = w*16 + (lane >> 2);
            unsigned a0 = Ps[(rbase    )*68 + kc    ];
            unsigned a1 = Ps[(rbase + 8)*68 + kc    ];
            unsigned a2 = Ps[(rbase    )*68 + kc + 4];
            unsigned a3 = Ps[(rbase + 8)*68 + kc + 4];
#pragma unroll
            for (int nf = 0; nf < 8; nf++){
                unsigned b0 = Vs[(kf*8 + (lane & 3)    )*72 + nf*8 + (lane >> 2)];
                unsigned b1 = Vs[(kf*8 + (lane & 3) + 4)*72 + nf*8 + (lane >> 2)];
                mma_tf32(O[nf][0], O[nf][1], O[nf][2], O[nf][3], a0, a1, a2, a3, b0, b1);
            }
        }
    }

    // epilogue
#pragma unroll
    for (int i = 0; i < 2; i++){
        int qn = q0 + w*16 + (lane >> 2) + i*8;
        if (qn >= CN) continue;
        float invl = 1.f / li[i];
        size_t base = ((size_t)b*CN + qn)*CC + h*64;
#pragma unroll
        for (int nf = 0; nf < 8; nf++){
            int c = nf*8 + (lane & 3)*2;
            *(float2*)(ao + base + c) = make_float2(O[nf][i*2]*invl, O[nf][i*2+1]*invl);
        }
    }
}

// ---------------- final: out = fused + BN(op_pw output), with transpose ----------------
__global__ void k_final(const float* __restrict__ fused, const float* __restrict__ o2t,
                        const float* __restrict__ bn, float* __restrict__ out)
{
    __shared__ float tile[32][33];
    int b = blockIdx.z;
    int p0 = blockIdx.x * 32, c0 = blockIdx.y * 32;
    int tx = threadIdx.x, ty = threadIdx.y;
#pragma unroll
    for (int i = 0; i < 4; i++){
        int p = p0 + ty + i*8;
        tile[ty + i*8][tx] = o2t[((size_t)b*CHW + p)*CC + c0 + tx];
    }
    __syncthreads();
#pragma unroll
    for (int i = 0; i < 4; i++){
        int c = c0 + ty + i*8;
        float s = bn[c] * rsqrtf(bn[3*CC+c] + EPS);
        float t = bn[CC+c] - bn[2*CC+c] * s;
        size_t idx = ((size_t)b*CC + c)*CHW + p0 + tx;
        out[idx] = fused[idx] + tile[tx][ty + i*8] * s + t;
    }
}

// ---------------- host ----------------
static void launch_gemm(int epi, const float* A, const float* Bw, float* Cm,
                        int M, int N, int K, const float* ep, const float* res)
{
    dim3 g(N/128, (M + 127)/128);
    switch (epi){
        case 0: k_gemm_tc<0><<<g,256>>>(A,Bw,Cm,M,N,K,ep,res); break;
        case 1: k_gemm_tc<1><<<g,256>>>(A,Bw,Cm,M,N,K,ep,res); break;
        case 2: k_gemm_tc<2><<<g,256>>>(A,Bw,Cm,M,N,K,ep,res); break;
        case 3: k_gemm_tc<3><<<g,256>>>(A,Bw,Cm,M,N,K,ep,res); break;
        case 4: k_gemm_tc<4><<<g,256>>>(A,Bw,Cm,M,N,K,ep,res); break;
    }
}

extern "C" void kernel_launch(void* const* d_in, const int* in_sizes, int n_in,
                              void* d_out, int out_size)
{
    const float* fused        = (const float*)d_in[0];
    const float* depth        = (const float*)d_in[1];
    const float* pg_dw_w      = (const float*)d_in[2];
    const float* pg_bn1       = (const float*)d_in[3];
    const float* pg_pw_w      = (const float*)d_in[4];
    const float* pg_bn2       = (const float*)d_in[5];
    const float* prompt_embed = (const float*)d_in[6];
    const float* pg_ln        = (const float*)d_in[7];
    const float* gp_dw_w      = (const float*)d_in[8];
    const float* gp_bn        = (const float*)d_in[9];
    const float* gp_pw_w      = (const float*)d_in[10];
    const float* gp_pw_b      = (const float*)d_in[11];
    const float* gp_weight    = (const float*)d_in[12];
    const float* ln1          = (const float*)d_in[13];
    const float* wq           = (const float*)d_in[14];
    const float* wk           = (const float*)d_in[15];
    const float* wv           = (const float*)d_in[16];
    const float* wo           = (const float*)d_in[17];
    const float* ln2          = (const float*)d_in[18];
    const float* mlp_w1       = (const float*)d_in[19];
    const float* mlp_b1       = (const float*)d_in[20];
    const float* mlp_w2       = (const float*)d_in[21];
    const float* mlp_b2       = (const float*)d_in[22];
    const float* op_dw_w      = (const float*)d_in[23];
    const float* op_bn1       = (const float*)d_in[24];
    const float* op_pw_w      = (const float*)d_in[25];
    const float* op_bn2       = (const float*)d_in[26];

    float *dw1,*dsf,*pp1t,*pp2t,*ds,*prm,*jdb,*jt,*xb,*qb,*kb,*vb,*aob,*hb,*enh,*o1c,*o1t,*o2t;
    cudaGetSymbolAddress((void**)&dw1,  g_dw1);
    cudaGetSymbolAddress((void**)&dsf,  g_dsf);
    cudaGetSymbolAddress((void**)&pp1t, g_pp1t);
    cudaGetSymbolAddress((void**)&pp2t, g_pp2t);
    cudaGetSymbolAddress((void**)&ds,   g_ds);
    cudaGetSymbolAddress((void**)&prm,  g_prompt);
    cudaGetSymbolAddress((void**)&jdb,  g_jd);
    cudaGetSymbolAddress((void**)&jt,   g_jt);
    cudaGetSymbolAddress((void**)&xb,   g_x);
    cudaGetSymbolAddress((void**)&qb,   g_q);
    cudaGetSymbolAddress((void**)&kb,   g_k);
    cudaGetSymbolAddress((void**)&vb,   g_v);
    cudaGetSymbolAddress((void**)&aob,  g_ao);
    cudaGetSymbolAddress((void**)&hb,   g_h);
    cudaGetSymbolAddress((void**)&enh,  g_enh);
    cudaGetSymbolAddress((void**)&o1c,  g_o1c);
    cudaGetSymbolAddress((void**)&o1t,  g_o1t);
    cudaGetSymbolAddress((void**)&o2t,  g_o2t);

    cudaFuncSetAttribute(k_attn, cudaFuncAttributeMaxDynamicSharedMemorySize, ATTN_SMEM);

    dim3 tgrid(CHW/32, CC/32, CB), tblk(32, 8);

    // --- DepthPromptGenerator + GeometryPriorGenerator shared dwconv ---
    k_dwconv_dual<<<(CB*CC*CHW)/256, 256>>>(depth, pg_dw_w, pg_bn1, dw1, gp_dw_w, gp_bn, dsf);
    k_cp_to_tok<<<tgrid, tblk>>>(dw1, pp1t, CHW, 0);
    launch_gemm(1, pp1t, pg_pw_w, pp2t, CB*CHW, CC, CC, pg_bn2, nullptr);   // bn2 + gelu
    k_gp_pw<<<(CB*CHW)/32, 256>>>(dsf, gp_pw_w, gp_pw_b, ds);
    k_prompt<<<CB*NPR, 256>>>(pp2t, prompt_embed, pg_ln, prm);
    k_jd<<<(CB*CN + 255)/256, 256>>>(ds, jdb);

    // --- assemble joint tokens ---
    k_copy_prompt<<<(CB*NPR*CC)/256, 256>>>(prm, jt);
    k_cp_to_tok<<<tgrid, tblk>>>(fused, jt, CN, NPR);

    // --- attention block ---
    k_ln<<<CB*CN, 256>>>(jt, ln1, xb);
    launch_gemm(0, xb, wq, qb, CB*CN, CC, CC, nullptr, nullptr);
    launch_gemm(0, xb, wk, kb, CB*CN, CC, CC, nullptr, nullptr);
    launch_gemm(0, xb, wv, vb, CB*CN, CC, CC, nullptr, nullptr);
    k_attn<<<dim3(9, CNH, CB), 256, ATTN_SMEM>>>(qb, kb, vb, jdb, gp_weight, aob);
    launch_gemm(4, aob, wo, jt, CB*CN, CC, CC, nullptr, jt);                // jt += ao@wo^T

    // --- MLP ---
    k_ln<<<CB*CN, 256>>>(jt, ln2, xb);
    launch_gemm(2, xb, mlp_w1, hb, CB*CN, HID, CC, mlp_b1, nullptr);        // bias + gelu
    launch_gemm(3, hb, mlp_w2, jt, CB*CN, CC, HID, mlp_b2, jt);             // bias + residual

    // --- out_proj ---
    k_tok_to_cp<<<tgrid, tblk>>>(jt, enh, CN, NPR);
    k_dwconv_dual<<<(CB*CC*CHW)/256, 256>>>(enh, op_dw_w, op_bn1, o1c, nullptr, nullptr, nullptr);
    k_cp_to_tok<<<tgrid, tblk>>>(o1c, o1t, CHW, 0);
    launch_gemm(0, o1t, op_pw_w, o2t, CB*CHW, CC, CC, nullptr, nullptr);
    k_final<<<tgrid, tblk>>>(fused, o2t, op_bn2, (float*)d_out);
}